// round 12
// baseline (speedup 1.0000x reference)
#include <cuda_runtime.h>
#include <math.h>

#define BB 8
#define NN 1024
#define DM 512
#define NH 8
#define HD 64
#define NS_TOK 1

typedef unsigned int uint;
typedef unsigned long long ull;

// Scratch (device globals: no allocations allowed in kernel_launch)
__device__ float g_qkv[(size_t)BB * NN * 3 * DM];   // [b][n][1536] : q|k|v
__device__ float g_attn[(size_t)BB * NN * DM];      // [b][n][512]

// ---------------------------------------------------------------------------
// tf32 split helpers (validated rounds 4-11)
// ---------------------------------------------------------------------------
__device__ __forceinline__ unsigned cvt_tf32(float x) {
    unsigned r;
    asm("cvt.rna.tf32.f32 %0, %1;" : "=r"(r) : "f"(x));
    return r;
}
__device__ __forceinline__ void split_tf32(float x, unsigned& hi, unsigned& lo) {
    hi = cvt_tf32(x);
    float rem = x - __uint_as_float(hi);
    lo = cvt_tf32(rem);
}
__device__ __forceinline__ void mma_tf32(
    float& c0, float& c1, float& c2, float& c3,
    unsigned a0, unsigned a1, unsigned a2, unsigned a3,
    unsigned b0, unsigned b1)
{
    asm("mma.sync.aligned.m16n8k8.row.col.f32.tf32.tf32.f32 "
        "{%0,%1,%2,%3}, {%4,%5,%6,%7}, {%8,%9}, {%0,%1,%2,%3};"
        : "+f"(c0), "+f"(c1), "+f"(c2), "+f"(c3)
        : "r"(a0), "r"(a1), "r"(a2), "r"(a3), "r"(b0), "r"(b1));
}

__device__ __forceinline__ float rcp_approx(float x) {
    float r;
    asm("rcp.approx.f32 %0, %1;" : "=f"(r) : "f"(x));
    return r;
}
__device__ __forceinline__ float ex2(float x) {
    float r;
    asm("ex2.approx.ftz.f32 %0, %1;" : "=f"(r) : "f"(x));
    return r;
}

// ---------------------------------------------------------------------------
// Packed f32x2 helpers (Phase A only; 2-lane axis = the thread's two pairs)
// ---------------------------------------------------------------------------
__device__ __forceinline__ ull ffma2(ull a, ull b, ull c) {
    ull d;
    asm("fma.rn.f32x2 %0, %1, %2, %3;" : "=l"(d) : "l"(a), "l"(b), "l"(c));
    return d;
}
__device__ __forceinline__ ull fmul2(ull a, ull b) {
    ull d;
    asm("mul.rn.f32x2 %0, %1, %2;" : "=l"(d) : "l"(a), "l"(b));
    return d;
}
__device__ __forceinline__ ull pack2(float x, float y) {
    ull d;
    asm("mov.b64 %0, {%1, %2};" : "=l"(d) : "f"(x), "f"(y));
    return d;
}
__device__ __forceinline__ float2 unpack2(ull v) {
    float2 r;
    asm("mov.b64 {%0, %1}, %2;" : "=f"(r.x), "=f"(r.y) : "l"(v));
    return r;
}

// ---------------------------------------------------------------------------
// Tensor-core GEMM v3 (round-9, measured 250.9us). 256 threads, double-
// buffered pre-split staging, one barrier per k-iter.
// ---------------------------------------------------------------------------
#define RP 20   // u32 per smem row (16 data + 4 pad)

__global__ __launch_bounds__(256) void gemm_tc(
    const float* __restrict__ A, const float* __restrict__ W,
    const float* __restrict__ bias, float* __restrict__ C,
    int M, int Nc, int K)
{
    extern __shared__ uint gsm[];
    const int tid  = threadIdx.x;
    const int wid  = tid >> 5, lane = tid & 31;
    const int g    = lane >> 2, t4 = lane & 3;
    const int wm   = wid & 1,  wn  = wid >> 1;
    const int brow = blockIdx.y * 128, bcol = blockIdx.x * 128;
    const int m_base = wm * 64, n_base = wn * 32;
    const int m0 = tid >> 2, kq = (tid & 3) * 4;

    float c[4][4][4];
#pragma unroll
    for (int mf = 0; mf < 4; mf++)
#pragma unroll
        for (int nf = 0; nf < 4; nf++)
#pragma unroll
            for (int r = 0; r < 4; r++) c[mf][nf][r] = 0.f;

    float4 ra0, ra1, rw0, rw1;
    {
        ra0 = *(const float4*)(A + (size_t)(brow + m0) * K + kq);
        ra1 = *(const float4*)(A + (size_t)(brow + m0 + 64) * K + kq);
        rw0 = *(const float4*)(W + (size_t)(bcol + m0) * K + kq);
        rw1 = *(const float4*)(W + (size_t)(bcol + m0 + 64) * K + kq);
    }

    int buf = 0;
    for (int k0 = 0; k0 < K; k0 += 16) {
        uint* S = gsm + buf * 10240;
        {
            uint4 h, l;
            split_tf32(ra0.x, h.x, l.x); split_tf32(ra0.y, h.y, l.y);
            split_tf32(ra0.z, h.z, l.z); split_tf32(ra0.w, h.w, l.w);
            *(uint4*)&S[m0 * RP + kq] = h;
            *(uint4*)&S[2560 + m0 * RP + kq] = l;
            split_tf32(ra1.x, h.x, l.x); split_tf32(ra1.y, h.y, l.y);
            split_tf32(ra1.z, h.z, l.z); split_tf32(ra1.w, h.w, l.w);
            *(uint4*)&S[(m0 + 64) * RP + kq] = h;
            *(uint4*)&S[2560 + (m0 + 64) * RP + kq] = l;
            split_tf32(rw0.x, h.x, l.x); split_tf32(rw0.y, h.y, l.y);
            split_tf32(rw0.z, h.z, l.z); split_tf32(rw0.w, h.w, l.w);
            *(uint4*)&S[5120 + m0 * RP + kq] = h;
            *(uint4*)&S[7680 + m0 * RP + kq] = l;
            split_tf32(rw1.x, h.x, l.x); split_tf32(rw1.y, h.y, l.y);
            split_tf32(rw1.z, h.z, l.z); split_tf32(rw1.w, h.w, l.w);
            *(uint4*)&S[5120 + (m0 + 64) * RP + kq] = h;
            *(uint4*)&S[7680 + (m0 + 64) * RP + kq] = l;
        }
        __syncthreads();

        if (k0 + 16 < K) {
            int kn = k0 + 16 + kq;
            ra0 = *(const float4*)(A + (size_t)(brow + m0) * K + kn);
            ra1 = *(const float4*)(A + (size_t)(brow + m0 + 64) * K + kn);
            rw0 = *(const float4*)(W + (size_t)(bcol + m0) * K + kn);
            rw1 = *(const float4*)(W + (size_t)(bcol + m0 + 64) * K + kn);
        }

        const uint* Ah = S, *Al = S + 2560, *Wh = S + 5120, *Wl = S + 7680;
#pragma unroll
        for (int ks = 0; ks < 16; ks += 8) {
            unsigned ah[4][4], al[4][4];
#pragma unroll
            for (int mf = 0; mf < 4; mf++) {
                int r0 = (m_base + mf * 16 + g) * RP;
                int r1 = r0 + 8 * RP;
                ah[mf][0] = Ah[r0 + ks + t4];     al[mf][0] = Al[r0 + ks + t4];
                ah[mf][1] = Ah[r1 + ks + t4];     al[mf][1] = Al[r1 + ks + t4];
                ah[mf][2] = Ah[r0 + ks + t4 + 4]; al[mf][2] = Al[r0 + ks + t4 + 4];
                ah[mf][3] = Ah[r1 + ks + t4 + 4]; al[mf][3] = Al[r1 + ks + t4 + 4];
            }
            unsigned bh[4][2], bl[4][2];
#pragma unroll
            for (int nf = 0; nf < 4; nf++) {
                int rn = (n_base + nf * 8 + g) * RP;
                bh[nf][0] = Wh[rn + ks + t4];     bl[nf][0] = Wl[rn + ks + t4];
                bh[nf][1] = Wh[rn + ks + t4 + 4]; bl[nf][1] = Wl[rn + ks + t4 + 4];
            }
#pragma unroll
            for (int mf = 0; mf < 4; mf++)
#pragma unroll
                for (int nf = 0; nf < 4; nf++) {
                    float* cc = c[mf][nf];
                    mma_tf32(cc[0], cc[1], cc[2], cc[3],
                             ah[mf][0], ah[mf][1], ah[mf][2], ah[mf][3],
                             bh[nf][0], bh[nf][1]);
                    mma_tf32(cc[0], cc[1], cc[2], cc[3],
                             ah[mf][0], ah[mf][1], ah[mf][2], ah[mf][3],
                             bl[nf][0], bl[nf][1]);
                    mma_tf32(cc[0], cc[1], cc[2], cc[3],
                             al[mf][0], al[mf][1], al[mf][2], al[mf][3],
                             bh[nf][0], bh[nf][1]);
                }
        }
        buf ^= 1;
    }

#pragma unroll
    for (int mf = 0; mf < 4; mf++) {
        int row0 = brow + m_base + mf * 16 + g;
#pragma unroll
        for (int nf = 0; nf < 4; nf++) {
            int col = bcol + n_base + nf * 8 + 2 * t4;
            float b0 = 0.f, b1 = 0.f;
            if (bias) { b0 = bias[col]; b1 = bias[col + 1]; }
            float2 lo, hi;
            lo.x = c[mf][nf][0] + b0; lo.y = c[mf][nf][1] + b1;
            hi.x = c[mf][nf][2] + b0; hi.y = c[mf][nf][3] + b1;
            *(float2*)(C + (size_t)row0 * Nc + col) = lo;
            *(float2*)(C + (size_t)(row0 + 8) * Nc + col) = hi;
        }
    }
}

// ---------------------------------------------------------------------------
// Fused relative-position-bias attention v10 (round-9 structure; Phase A
// rewritten in packed f32x2 over the (pair0, pair1) lane axis; weights
// pre-DUPLICATED in smem so LDS.128 yields (w,w) packed operands directly).
// Smem floats (53864 = 215456 B):
//   k_s [32][524] @0, v_s @16768, bias_s[8][32][37] @33536, lg_s[8][32][36]
//   @43008, corr_s @52224, l_s @52480, ci @52736, cj @52864, w1d @52992(256),
//   b1d @53248(64), w2d @53312(512), b2 @53824(8), mask @53832(32)
// ---------------------------------------------------------------------------
#define LOG2E 1.4426950408889634f

__global__ __launch_bounds__(512, 1) void attn_bias_kernel(
    const float* __restrict__ qkv, const float* __restrict__ coords,
    const unsigned char* __restrict__ kpm,
    const float* __restrict__ w1, const float* __restrict__ b1,
    const float* __restrict__ w2, const float* __restrict__ b2,
    const float* __restrict__ cscales, const float* __restrict__ alphap,
    float* __restrict__ outp)
{
    extern __shared__ float sm[];
    float* k_s    = sm;            // [j][524]
    float* v_s    = sm + 16768;    // [j][524]
    float* bias_s = sm + 33536;    // [h][i][37]
    float* lg_s   = sm + 43008;    // [h][i][36]
    float* corr_s = sm + 52224;    // 256
    float* l_s    = sm + 52480;    // 256
    float* ci_s   = sm + 52736;    // 32*4
    float* cj_s   = sm + 52864;    // 32*4
    float* w1d    = sm + 52992;    // [kk][8]  (x,x,y,y,z,z,w,w)
    float* b1d    = sm + 53248;    // [kk][2]
    float* w2d    = sm + 53312;    // [kk][16] (w0,w0,...,w7,w7) alpha*log2e
    float* b2_s   = sm + 53824;    // 8 (alpha*log2e folded)
    float* mask_s = sm + 53832;    // 32

    const int tid  = threadIdx.x;
    const int lane = tid & 31;
    const int wid  = tid >> 5;
    const int h    = wid >> 1;
    const int mh   = wid & 1;
    const int g    = lane >> 2;
    const int t4   = lane & 3;
    const int b    = blockIdx.x >> 5;
    const int i0   = (blockIdx.x & 31) * 32;
    const float alpha = alphap[0];

    const int sr     = tid >> 1;          // 0..255
    const int sjh    = (tid & 1) * 16;
    const int sbaseL = sr * 36;
    const int sbaseB = sr * 37;

    if (tid < 128) {
        int kk = tid >> 2, f = tid & 3;
        float v = w1[tid];
        w1d[kk * 8 + f * 2]     = v;
        w1d[kk * 8 + f * 2 + 1] = v;
    }
    if (tid < 64) b1d[tid] = b1[tid >> 1];
    {   // w2d: 512 entries, 512 threads
        int kk = tid >> 4, hh = (tid >> 1) & 7;
        w2d[tid] = alpha * LOG2E * w2[hh * 32 + kk];
    }
    if (tid < 8) b2_s[tid] = alpha * LOG2E * b2[tid];
    if (tid < 32) {
        int ig = i0 + tid;
        ci_s[tid * 4 + 0] = coords[((size_t)b * NN + ig) * 3 + 0] / cscales[0];
        ci_s[tid * 4 + 1] = coords[((size_t)b * NN + ig) * 3 + 1] / cscales[1];
        ci_s[tid * 4 + 2] = coords[((size_t)b * NN + ig) * 3 + 2] / cscales[2];
        ci_s[tid * 4 + 3] = 0.f;
    }

    // Q elements feeding QK A-fragments (scale 1/8 * log2e folded)
    const float QSC = 0.125f * LOG2E;
    float qa[8][4];
    {
        const float* q0 = qkv + ((size_t)(b * NN + i0 + mh * 16 + g)) * 1536 + h * 64;
        const float* q8 = q0 + 8 * 1536;
#pragma unroll
        for (int ks = 0; ks < 8; ks++) {
            qa[ks][0] = q0[ks * 8 + t4]     * QSC;
            qa[ks][1] = q8[ks * 8 + t4]     * QSC;
            qa[ks][2] = q0[ks * 8 + t4 + 4] * QSC;
            qa[ks][3] = q8[ks * 8 + t4 + 4] * QSC;
        }
    }

    // Packed constants for the gelu poly (A-S 7.1.28, validated round 9)
    const ull cC0 = pack2(0.0000430638f, 0.0000430638f);
    const ull cC1 = pack2(0.0002765672f, 0.0002765672f);
    const ull cC2 = pack2(0.0001520143f, 0.0001520143f);
    const ull cC3 = pack2(0.0092705272f, 0.0092705272f);
    const ull cC4 = pack2(0.0422820123f, 0.0422820123f);
    const ull cC5 = pack2(0.0705230784f, 0.0705230784f);
    const ull cONE = pack2(1.0f, 1.0f);
    const ull cSQH = pack2(0.70710678118654752f, 0.70710678118654752f);

    float oacc[8][4];
#pragma unroll
    for (int nf = 0; nf < 8; nf++)
#pragma unroll
        for (int r = 0; r < 4; r++) oacc[nf][r] = 0.f;
    float mrun = -INFINITY, lrun = 0.f;

    __syncthreads();

    for (int j0 = 0; j0 < NN; j0 += 32) {
        // ---- stage K/V tile (fp32) ----
#pragma unroll
        for (int t = tid; t < 4096; t += 512) {
            int jj = t >> 7, c4 = (t & 127) * 4;
            const float* src = qkv + ((size_t)(b * NN + j0 + jj)) * 1536;
            *(float4*)(k_s + jj * 524 + c4) = *(const float4*)(src + 512 + c4);
            *(float4*)(v_s + jj * 524 + c4) = *(const float4*)(src + 1024 + c4);
        }
        if (tid < 32) {
            int jg = j0 + tid;
            mask_s[tid] = kpm[(size_t)b * NN + jg] ? 1.f : 0.f;
            cj_s[tid * 4 + 0] = coords[((size_t)b * NN + jg) * 3 + 0] / cscales[0];
            cj_s[tid * 4 + 1] = coords[((size_t)b * NN + jg) * 3 + 1] / cscales[1];
            cj_s[tid * 4 + 2] = coords[((size_t)b * NN + jg) * 3 + 2] / cscales[2];
            cj_s[tid * 4 + 3] = 0.f;
        }
        __syncthreads();

        // ---- QK^T via tf32 split MMA (validated) ----
        {
            float c[4][4];
#pragma unroll
            for (int nf = 0; nf < 4; nf++)
#pragma unroll
                for (int r = 0; r < 4; r++) c[nf][r] = 0.f;
#pragma unroll
            for (int ks = 0; ks < 8; ks++) {
                uint ah[4], al[4];
                split_tf32(qa[ks][0], ah[0], al[0]);
                split_tf32(qa[ks][1], ah[1], al[1]);
                split_tf32(qa[ks][2], ah[2], al[2]);
                split_tf32(qa[ks][3], ah[3], al[3]);
#pragma unroll
                for (int nf = 0; nf < 4; nf++) {
                    const float* kr = k_s + (nf * 8 + g) * 524 + h * 64 + ks * 8;
                    uint bh0, bl0, bh1, bl1;
                    split_tf32(kr[t4],     bh0, bl0);
                    split_tf32(kr[t4 + 4], bh1, bl1);
                    mma_tf32(c[nf][0], c[nf][1], c[nf][2], c[nf][3],
                             ah[0], ah[1], ah[2], ah[3], bh0, bh1);
                    mma_tf32(c[nf][0], c[nf][1], c[nf][2], c[nf][3],
                             ah[0], ah[1], ah[2], ah[3], bl0, bl1);
                    mma_tf32(c[nf][0], c[nf][1], c[nf][2], c[nf][3],
                             al[0], al[1], al[2], al[3], bh0, bh1);
                }
            }
            const int rowL = h * 1152 + (mh * 16 + g) * 36;
#pragma unroll
            for (int nf = 0; nf < 4; nf++) {
                *(float2*)(lg_s + rowL + nf * 8 + 2 * t4) =
                    make_float2(c[nf][0], c[nf][1]);
                *(float2*)(lg_s + rowL + 8 * 36 + nf * 8 + 2 * t4) =
                    make_float2(c[nf][2], c[nf][3]);
            }
        }

        // ---- Phase A: bias MLP, packed f32x2 over (pair0, pair1) lanes ----
        {
            const int ii  = tid & 31;
            const int jj0 = tid >> 5;
            const int jj1 = jj0 + 16;
            const float cix = ci_s[ii * 4 + 0];
            const float ciy = ci_s[ii * 4 + 1];
            const float ciz = ci_s[ii * 4 + 2];
            const float dx0 = cix - cj_s[jj0 * 4 + 0];
            const float dy0 = ciy - cj_s[jj0 * 4 + 1];
            const float dz0 = ciz - cj_s[jj0 * 4 + 2];
            const float dx1 = cix - cj_s[jj1 * 4 + 0];
            const float dy1 = ciy - cj_s[jj1 * 4 + 1];
            const float dz1 = ciz - cj_s[jj1 * 4 + 2];
            const float di0 = sqrtf(fmaf(dx0, dx0, fmaf(dy0, dy0, dz0 * dz0)));
            const float di1 = sqrtf(fmaf(dx1, dx1, fmaf(dy1, dy1, dz1 * dz1)));
            const ull dxp = pack2(dx0, dx1);
            const ull dyp = pack2(dy0, dy1);
            const ull dzp = pack2(dz0, dz1);
            const ull dip = pack2(di0, di1);

            ull boP[8];
#pragma unroll
            for (int hh = 0; hh < 8; hh++)
                boP[hh] = pack2(b2_s[hh], b2_s[hh]);

#pragma unroll 4
            for (int kk = 0; kk < 32; kk++) {
                const ull* w1p = (const ull*)&w1d[kk * 8];   // 2x LDS.128
                ull tP = *(const ull*)&b1d[kk * 2];
                tP = ffma2(w1p[0], dxp, tP);
                tP = ffma2(w1p[1], dyp, tP);
                tP = ffma2(w1p[2], dzp, tP);
                tP = ffma2(w1p[3], dip, tP);

                // packed gelu (erf via A-S 7.1.28: 1-(poly6)^-16)
                ull xsP = fmul2(tP, cSQH);
                ull axP = xsP & 0x7FFFFFFF7FFFFFFFull;
                ull t6 = cC0;
                t6 = ffma2(t6, axP, cC1);
                t6 = ffma2(t6, axP, cC2);
                t6 = ffma2(t6, axP, cC3);
                t6 = ffma2(t6, axP, cC4);
                t6 = ffma2(t6, axP, cC5);
                t6 = ffma2(t6, axP, cONE);
                ull p2 = fmul2(t6, t6);
                ull p4 = fmul2(p2, p2);
                ull p8 = fmul2(p4, p4);
                ull p16 = fmul2(p8, p8);
                float2 pv = unpack2(p16);
                float2 xv = unpack2(tP);
                float er0 = copysignf(1.f - rcp_approx(pv.x), xv.x);
                float er1 = copysignf(1.f - rcp_approx(pv.y), xv.y);
                float g0 = 0.5f * xv.x * (1.f + er0);
                float g1 = 0.5f * xv.y * (1.f + er1);
                ull gP = pack2(g0, g1);

                const ull* w2p = (const ull*)&w2d[kk * 16];  // 4x LDS.128
                boP[0] = ffma2(gP, w2p[0], boP[0]);
                boP[1] = ffma2(gP, w2p[1], boP[1]);
                boP[2] = ffma2(gP, w2p[2], boP[2]);
                boP[3] = ffma2(gP, w2p[3], boP[3]);
                boP[4] = ffma2(gP, w2p[4], boP[4]);
                boP[5] = ffma2(gP, w2p[5], boP[5]);
                boP[6] = ffma2(gP, w2p[6], boP[6]);
                boP[7] = ffma2(gP, w2p[7], boP[7]);
            }

            const float zf0 =
                ((i0 + ii) >= NS_TOK && (j0 + jj0) >= NS_TOK) ? 1.f : 0.f;
            const float zf1 =
                ((i0 + ii) >= NS_TOK && (j0 + jj1) >= NS_TOK) ? 1.f : 0.f;
#pragma unroll
            for (int hh = 0; hh < 8; hh++) {
                float2 v = unpack2(boP[hh]);
                bias_s[hh * 1184 + ii * 37 + jj0] = v.x * zf0;
                bias_s[hh * 1184 + ii * 37 + jj1] = v.y * zf1;
            }
        }
        __syncthreads();

        // ---- softmax (base-2): 2 threads per row; p in-place into lg_s ----
        {
            float lg[16];
            float4 L;
#pragma unroll
            for (int q = 0; q < 4; q++) {
                L = *(const float4*)(lg_s + sbaseL + sjh + 4 * q);
                lg[4*q+0] = L.x; lg[4*q+1] = L.y; lg[4*q+2] = L.z; lg[4*q+3] = L.w;
            }
            float tmax = -INFINITY;
#pragma unroll
            for (int c = 0; c < 16; c++) {
                float x = lg[c] + bias_s[sbaseB + sjh + c];
                if (mask_s[sjh + c] > 0.5f) x = -1e30f;
                lg[c] = x;
                tmax = fmaxf(tmax, x);
            }
            tmax = fmaxf(tmax, __shfl_xor_sync(0xffffffffu, tmax, 1));
            float mnew = fmaxf(mrun, tmax);
            float corr = ex2(mrun - mnew);
            mrun = mnew;
            lrun *= corr;
            float ps = 0.f;
#pragma unroll
            for (int q = 0; q < 4; q++) {
                float4 P;
                P.x = ex2(lg[4*q+0] - mrun);
                P.y = ex2(lg[4*q+1] - mrun);
                P.z = ex2(lg[4*q+2] - mrun);
                P.w = ex2(lg[4*q+3] - mrun);
                ps += (P.x + P.y) + (P.z + P.w);
                *(float4*)(lg_s + sbaseL + sjh + 4 * q) = P;
            }
            ps += __shfl_xor_sync(0xffffffffu, ps, 1);
            lrun += ps;
            corr_s[sr] = corr;
        }
        __syncthreads();

        // ---- AV via tf32 split MMA (validated) ----
        {
            float corr0 = corr_s[h * 32 + mh * 16 + g];
            float corr1 = corr_s[h * 32 + mh * 16 + g + 8];
#pragma unroll
            for (int nf = 0; nf < 8; nf++) {
                oacc[nf][0] *= corr0; oacc[nf][1] *= corr0;
                oacc[nf][2] *= corr1; oacc[nf][3] *= corr1;
            }
            const int prow = h * 1152 + (mh * 16 + g) * 36;
#pragma unroll
            for (int ks = 0; ks < 4; ks++) {
                uint pah[4], pal[4];
                split_tf32(lg_s[prow + ks * 8 + t4],              pah[0], pal[0]);
                split_tf32(lg_s[prow + 8 * 36 + ks * 8 + t4],     pah[1], pal[1]);
                split_tf32(lg_s[prow + ks * 8 + t4 + 4],          pah[2], pal[2]);
                split_tf32(lg_s[prow + 8 * 36 + ks * 8 + t4 + 4], pah[3], pal[3]);
                const float* vb0 = v_s + (ks * 8 + t4) * 524 + h * 64;
                const float* vb1 = v_s + (ks * 8 + t4 + 4) * 524 + h * 64;
#pragma unroll
                for (int nf = 0; nf < 8; nf++) {
                    uint bh0, bl0, bh1, bl1;
                    split_tf32(vb0[nf * 8 + g], bh0, bl0);
                    split_tf32(vb1[nf * 8 + g], bh1, bl1);
                    mma_tf32(oacc[nf][0], oacc[nf][1], oacc[nf][2], oacc[nf][3],
                             pah[0], pah[1], pah[2], pah[3], bh0, bh1);
                    mma_tf32(oacc[nf][0], oacc[nf][1], oacc[nf][2], oacc[nf][3],
                             pah[0], pah[1], pah[2], pah[3], bl0, bl1);
                    mma_tf32(oacc[nf][0], oacc[nf][1], oacc[nf][2], oacc[nf][3],
                             pal[0], pal[1], pal[2], pal[3], bh0, bh1);
                }
            }
        }
        __syncthreads();
    }

    if ((tid & 1) == 0) l_s[sr] = lrun;
    __syncthreads();

    {
        float inv0 = 1.f / l_s[h * 32 + mh * 16 + g];
        float inv1 = 1.f / l_s[h * 32 + mh * 16 + g + 8];
        float* o0 = outp + ((size_t)(b * NN + i0 + mh * 16 + g)) * 512 + h * 64;
        float* o1 = o0 + 8 * 512;
#pragma unroll
        for (int nf = 0; nf < 8; nf++) {
            *(float2*)(o0 + nf * 8 + 2 * t4) =
                make_float2(oacc[nf][0] * inv0, oacc[nf][1] * inv0);
            *(float2*)(o1 + nf * 8 + 2 * t4) =
                make_float2(oacc[nf][2] * inv1, oacc[nf][3] * inv1);
        }
    }
}

// ---------------------------------------------------------------------------
extern "C" void kernel_launch(void* const* d_in, const int* in_sizes, int n_in,
                              void* d_out, int out_size)
{
    const float* x      = (const float*)d_in[0];
    const float* coords = (const float*)d_in[1];
    const unsigned char* kpm = (const unsigned char*)d_in[2];
    const float* qkv_w  = (const float*)d_in[3];
    const float* out_w  = (const float*)d_in[4];
    const float* out_b  = (const float*)d_in[5];
    const float* alpha  = (const float*)d_in[6];
    const float* w1     = (const float*)d_in[7];
    const float* b1     = (const float*)d_in[8];
    const float* w2     = (const float*)d_in[9];
    const float* b2     = (const float*)d_in[10];
    const float* cs     = (const float*)d_in[11];
    float* out = (float*)d_out;

    float* qkvp = nullptr;
    float* attnp = nullptr;
    cudaGetSymbolAddress((void**)&qkvp, g_qkv);
    cudaGetSymbolAddress((void**)&attnp, g_attn);

    const int GSMEM = 2 * 10240 * 4;   // 81920 B (gemm)
    cudaFuncSetAttribute(gemm_tc,
                         cudaFuncAttributeMaxDynamicSharedMemorySize, GSMEM);
    const int SMEM = 53864 * 4;        // 215456 B (attention)
    cudaFuncSetAttribute(attn_bias_kernel,
                         cudaFuncAttributeMaxDynamicSharedMemorySize, SMEM);

    // 1) QKV projection: [8192,512] @ [512,1536]
    dim3 g1(1536 / 128, 8192 / 128);
    gemm_tc<<<g1, 256, GSMEM>>>(x, qkv_w, nullptr, qkvp, BB * NN, 3 * DM, DM);

    // 2) Fused bias + attention (packed-f32x2 Phase A)
    attn_bias_kernel<<<BB * (NN / 32), 512, SMEM>>>(
        qkvp, coords, kpm, w1, b1, w2, b2, cs, alpha, attnp);

    // 3) Output projection: [8192,512] @ [512,512] + bias
    dim3 g3(512 / 128, 8192 / 128);
    gemm_tc<<<g3, 256, GSMEM>>>(attnp, out_w, out_b, out, BB * NN, DM, DM);
}

// round 13
// speedup vs baseline: 1.3351x; 1.3351x over previous
#include <cuda_runtime.h>
#include <math.h>

#define BB 8
#define NN 1024
#define DM 512
#define NH 8
#define HD 64
#define NS_TOK 1

typedef unsigned int uint;

// Scratch (device globals: no allocations allowed in kernel_launch)
__device__ float g_qkv[(size_t)BB * NN * 3 * DM];   // [b][n][1536] : q|k|v
__device__ float g_attn[(size_t)BB * NN * DM];      // [b][n][512]

// ---------------------------------------------------------------------------
// tf32 split helpers (validated rounds 4-11)
// ---------------------------------------------------------------------------
__device__ __forceinline__ unsigned cvt_tf32(float x) {
    unsigned r;
    asm("cvt.rna.tf32.f32 %0, %1;" : "=r"(r) : "f"(x));
    return r;
}
__device__ __forceinline__ void split_tf32(float x, unsigned& hi, unsigned& lo) {
    hi = cvt_tf32(x);
    float rem = x - __uint_as_float(hi);
    lo = cvt_tf32(rem);
}
__device__ __forceinline__ void mma_tf32(
    float& c0, float& c1, float& c2, float& c3,
    unsigned a0, unsigned a1, unsigned a2, unsigned a3,
    unsigned b0, unsigned b1)
{
    asm("mma.sync.aligned.m16n8k8.row.col.f32.tf32.tf32.f32 "
        "{%0,%1,%2,%3}, {%4,%5,%6,%7}, {%8,%9}, {%0,%1,%2,%3};"
        : "+f"(c0), "+f"(c1), "+f"(c2), "+f"(c3)
        : "r"(a0), "r"(a1), "r"(a2), "r"(a3), "r"(b0), "r"(b1));
}

__device__ __forceinline__ float rcp_approx(float x) {
    float r;
    asm("rcp.approx.f32 %0, %1;" : "=f"(r) : "f"(x));
    return r;
}
__device__ __forceinline__ float ex2(float x) {
    float r;
    asm("ex2.approx.ftz.f32 %0, %1;" : "=f"(r) : "f"(x));
    return r;
}

// Named barriers (producer-consumer across warp groups)
__device__ __forceinline__ void nbar_sync(int id, int cnt) {
    asm volatile("bar.sync %0, %1;" :: "r"(id), "r"(cnt) : "memory");
}
__device__ __forceinline__ void nbar_arrive(int id, int cnt) {
    asm volatile("bar.arrive %0, %1;" :: "r"(id), "r"(cnt) : "memory");
}

// gelu with erf via Abramowitz-Stegun 7.1.28 (|err| <= 3e-7, 1 MUFU).
__device__ __forceinline__ float gelu_ns(float x) {
    float xs = x * 0.70710678118654752f;
    float ax = fabsf(xs);
    float t = 0.0000430638f;
    t = fmaf(t, ax, 0.0002765672f);
    t = fmaf(t, ax, 0.0001520143f);
    t = fmaf(t, ax, 0.0092705272f);
    t = fmaf(t, ax, 0.0422820123f);
    t = fmaf(t, ax, 0.0705230784f);
    t = fmaf(t, ax, 1.0f);
    float t2 = t * t;
    float t4 = t2 * t2;
    float t8 = t4 * t4;
    float t16 = t8 * t8;
    float er = 1.0f - rcp_approx(t16);
    er = copysignf(er, xs);
    return 0.5f * x * (1.0f + er);
}

// ---------------------------------------------------------------------------
// Tensor-core GEMM v3 (round-9, measured 250.9us). Unchanged.
// ---------------------------------------------------------------------------
#define RP 20   // u32 per smem row (16 data + 4 pad)

__global__ __launch_bounds__(256) void gemm_tc(
    const float* __restrict__ A, const float* __restrict__ W,
    const float* __restrict__ bias, float* __restrict__ C,
    int M, int Nc, int K)
{
    extern __shared__ uint gsm[];
    const int tid  = threadIdx.x;
    const int wid  = tid >> 5, lane = tid & 31;
    const int g    = lane >> 2, t4 = lane & 3;
    const int wm   = wid & 1,  wn  = wid >> 1;
    const int brow = blockIdx.y * 128, bcol = blockIdx.x * 128;
    const int m_base = wm * 64, n_base = wn * 32;
    const int m0 = tid >> 2, kq = (tid & 3) * 4;

    float c[4][4][4];
#pragma unroll
    for (int mf = 0; mf < 4; mf++)
#pragma unroll
        for (int nf = 0; nf < 4; nf++)
#pragma unroll
            for (int r = 0; r < 4; r++) c[mf][nf][r] = 0.f;

    float4 ra0, ra1, rw0, rw1;
    {
        ra0 = *(const float4*)(A + (size_t)(brow + m0) * K + kq);
        ra1 = *(const float4*)(A + (size_t)(brow + m0 + 64) * K + kq);
        rw0 = *(const float4*)(W + (size_t)(bcol + m0) * K + kq);
        rw1 = *(const float4*)(W + (size_t)(bcol + m0 + 64) * K + kq);
    }

    int buf = 0;
    for (int k0 = 0; k0 < K; k0 += 16) {
        uint* S = gsm + buf * 10240;
        {
            uint4 h, l;
            split_tf32(ra0.x, h.x, l.x); split_tf32(ra0.y, h.y, l.y);
            split_tf32(ra0.z, h.z, l.z); split_tf32(ra0.w, h.w, l.w);
            *(uint4*)&S[m0 * RP + kq] = h;
            *(uint4*)&S[2560 + m0 * RP + kq] = l;
            split_tf32(ra1.x, h.x, l.x); split_tf32(ra1.y, h.y, l.y);
            split_tf32(ra1.z, h.z, l.z); split_tf32(ra1.w, h.w, l.w);
            *(uint4*)&S[(m0 + 64) * RP + kq] = h;
            *(uint4*)&S[2560 + (m0 + 64) * RP + kq] = l;
            split_tf32(rw0.x, h.x, l.x); split_tf32(rw0.y, h.y, l.y);
            split_tf32(rw0.z, h.z, l.z); split_tf32(rw0.w, h.w, l.w);
            *(uint4*)&S[5120 + m0 * RP + kq] = h;
            *(uint4*)&S[7680 + m0 * RP + kq] = l;
            split_tf32(rw1.x, h.x, l.x); split_tf32(rw1.y, h.y, l.y);
            split_tf32(rw1.z, h.z, l.z); split_tf32(rw1.w, h.w, l.w);
            *(uint4*)&S[5120 + (m0 + 64) * RP + kq] = h;
            *(uint4*)&S[7680 + (m0 + 64) * RP + kq] = l;
        }
        __syncthreads();

        if (k0 + 16 < K) {
            int kn = k0 + 16 + kq;
            ra0 = *(const float4*)(A + (size_t)(brow + m0) * K + kn);
            ra1 = *(const float4*)(A + (size_t)(brow + m0 + 64) * K + kn);
            rw0 = *(const float4*)(W + (size_t)(bcol + m0) * K + kn);
            rw1 = *(const float4*)(W + (size_t)(bcol + m0 + 64) * K + kn);
        }

        const uint* Ah = S, *Al = S + 2560, *Wh = S + 5120, *Wl = S + 7680;
#pragma unroll
        for (int ks = 0; ks < 16; ks += 8) {
            unsigned ah[4][4], al[4][4];
#pragma unroll
            for (int mf = 0; mf < 4; mf++) {
                int r0 = (m_base + mf * 16 + g) * RP;
                int r1 = r0 + 8 * RP;
                ah[mf][0] = Ah[r0 + ks + t4];     al[mf][0] = Al[r0 + ks + t4];
                ah[mf][1] = Ah[r1 + ks + t4];     al[mf][1] = Al[r1 + ks + t4];
                ah[mf][2] = Ah[r0 + ks + t4 + 4]; al[mf][2] = Al[r0 + ks + t4 + 4];
                ah[mf][3] = Ah[r1 + ks + t4 + 4]; al[mf][3] = Al[r1 + ks + t4 + 4];
            }
            unsigned bh[4][2], bl[4][2];
#pragma unroll
            for (int nf = 0; nf < 4; nf++) {
                int rn = (n_base + nf * 8 + g) * RP;
                bh[nf][0] = Wh[rn + ks + t4];     bl[nf][0] = Wl[rn + ks + t4];
                bh[nf][1] = Wh[rn + ks + t4 + 4]; bl[nf][1] = Wl[rn + ks + t4 + 4];
            }
#pragma unroll
            for (int mf = 0; mf < 4; mf++)
#pragma unroll
                for (int nf = 0; nf < 4; nf++) {
                    float* cc = c[mf][nf];
                    mma_tf32(cc[0], cc[1], cc[2], cc[3],
                             ah[mf][0], ah[mf][1], ah[mf][2], ah[mf][3],
                             bh[nf][0], bh[nf][1]);
                    mma_tf32(cc[0], cc[1], cc[2], cc[3],
                             ah[mf][0], ah[mf][1], ah[mf][2], ah[mf][3],
                             bl[nf][0], bl[nf][1]);
                    mma_tf32(cc[0], cc[1], cc[2], cc[3],
                             al[mf][0], al[mf][1], al[mf][2], al[mf][3],
                             bh[nf][0], bh[nf][1]);
                }
        }
        buf ^= 1;
    }

#pragma unroll
    for (int mf = 0; mf < 4; mf++) {
        int row0 = brow + m_base + mf * 16 + g;
#pragma unroll
        for (int nf = 0; nf < 4; nf++) {
            int col = bcol + n_base + nf * 8 + 2 * t4;
            float b0 = 0.f, b1 = 0.f;
            if (bias) { b0 = bias[col]; b1 = bias[col + 1]; }
            float2 lo, hi;
            lo.x = c[mf][nf][0] + b0; lo.y = c[mf][nf][1] + b1;
            hi.x = c[mf][nf][2] + b0; hi.y = c[mf][nf][3] + b1;
            *(float2*)(C + (size_t)row0 * Nc + col) = lo;
            *(float2*)(C + (size_t)(row0 + 8) * Nc + col) = hi;
        }
    }
}

// ---------------------------------------------------------------------------
// Fused relative-position-bias attention v11: WARP-SPECIALIZED.
// 512 threads. C group = warps 0-7 (tid<256): warp h owns head h, all 32
// rows (2 m-frags). P group = warps 8-15 (tid>=256): bias MLP producer,
// 4 pairs/thread (shared ii). Single bias_s buffer; named barriers:
//   id 1 (512): P arrive after bias(t) written; C sync before softmax(t)
//   id 2 (512): C arrive after softmax(t) read bias; P sync before bias(t+1)
//   id 3 (256): C-internal (staging / buffer reuse)
// Numerics identical to round 9 (tf32 split MMA, base-2 softmax, gelu_ns).
// Smem floats (53192 = 212768 B): offsets in code.
// ---------------------------------------------------------------------------
#define LOG2E 1.4426950408889634f

__global__ __launch_bounds__(512, 1) void attn_bias_kernel(
    const float* __restrict__ qkv, const float* __restrict__ coords,
    const unsigned char* __restrict__ kpm,
    const float* __restrict__ w1, const float* __restrict__ b1,
    const float* __restrict__ w2, const float* __restrict__ b2,
    const float* __restrict__ cscales, const float* __restrict__ alphap,
    float* __restrict__ outp)
{
    extern __shared__ float sm[];
    float* k_s    = sm;            // [32][524]
    float* v_s    = sm + 16768;    // [32][524]
    float* bias_s = sm + 33536;    // [8][32][37]
    float* lg_s   = sm + 43008;    // [8][32][36]
    float* corr_s = sm + 52224;    // 256
    float* l_s    = sm + 52480;    // 256
    float* w1_s   = sm + 52736;    // 128
    float* b1_s   = sm + 52864;    // 32
    float* w2t_s  = sm + 52896;    // [kk][8] alpha*log2e folded (256)
    float* b2_s   = sm + 53152;    // 8
    float* mask_s = sm + 53160;    // 32

    const int tid  = threadIdx.x;
    const int lane = tid & 31;
    const int b    = blockIdx.x >> 5;
    const int i0   = (blockIdx.x & 31) * 32;
    const float alpha = alphap[0];

    if (tid < 128) w1_s[tid] = w1[tid];
    if (tid < 32)  b1_s[tid] = b1[tid];
    if (tid < 256) w2t_s[tid] = alpha * LOG2E * w2[(tid & 7) * 32 + (tid >> 3)];
    if (tid < 8)   b2_s[tid] = alpha * LOG2E * b2[tid];
    __syncthreads();

    if (tid >= 256) {
        // ================= P group: bias MLP producer =================
        const int tid2 = tid - 256;
        const int ii   = tid2 & 31;
        const int jjb  = tid2 >> 5;          // 0..7
        const float icx = 1.f / cscales[0];
        const float icy = 1.f / cscales[1];
        const float icz = 1.f / cscales[2];
        const float cix = coords[((size_t)b * NN + i0 + ii) * 3 + 0] * icx;
        const float ciy = coords[((size_t)b * NN + i0 + ii) * 3 + 1] * icy;
        const float ciz = coords[((size_t)b * NN + i0 + ii) * 3 + 2] * icz;
        const float zfi = ((i0 + ii) >= NS_TOK) ? 1.f : 0.f;

        for (int t = 0; t < 32; t++) {
            const int j0 = t * 32;
            if (t > 0) nbar_sync(2, 512);    // wait: bias buffer free

            float dx[4], dy[4], dz[4], di[4], zf[4];
#pragma unroll
            for (int q = 0; q < 4; q++) {
                int jg = j0 + jjb + 8 * q;
                const float* cp = coords + ((size_t)b * NN + jg) * 3;
                dx[q] = cix - cp[0] * icx;
                dy[q] = ciy - cp[1] * icy;
                dz[q] = ciz - cp[2] * icz;
                di[q] = sqrtf(fmaf(dx[q], dx[q],
                              fmaf(dy[q], dy[q], dz[q] * dz[q])));
                zf[q] = (jg >= NS_TOK) ? zfi : 0.f;
            }

            float bo[4][8];
#pragma unroll
            for (int q = 0; q < 4; q++)
#pragma unroll
                for (int hh = 0; hh < 8; hh++) bo[q][hh] = b2_s[hh];

#pragma unroll 4
            for (int kk = 0; kk < 32; kk++) {
                float4 wv = *(const float4*)&w1_s[kk * 4];
                float bb  = b1_s[kk];
                float4 wa = *(const float4*)&w2t_s[kk * 8];
                float4 wb = *(const float4*)&w2t_s[kk * 8 + 4];
#pragma unroll
                for (int q = 0; q < 4; q++) {
                    float t2 = bb;
                    t2 = fmaf(wv.x, dx[q], t2);
                    t2 = fmaf(wv.y, dy[q], t2);
                    t2 = fmaf(wv.z, dz[q], t2);
                    t2 = fmaf(wv.w, di[q], t2);
                    float gl = gelu_ns(t2);
                    bo[q][0] = fmaf(gl, wa.x, bo[q][0]);
                    bo[q][1] = fmaf(gl, wa.y, bo[q][1]);
                    bo[q][2] = fmaf(gl, wa.z, bo[q][2]);
                    bo[q][3] = fmaf(gl, wa.w, bo[q][3]);
                    bo[q][4] = fmaf(gl, wb.x, bo[q][4]);
                    bo[q][5] = fmaf(gl, wb.y, bo[q][5]);
                    bo[q][6] = fmaf(gl, wb.z, bo[q][6]);
                    bo[q][7] = fmaf(gl, wb.w, bo[q][7]);
                }
            }
#pragma unroll
            for (int q = 0; q < 4; q++) {
                int jj = jjb + 8 * q;
#pragma unroll
                for (int hh = 0; hh < 8; hh++)
                    bias_s[hh * 1184 + ii * 37 + jj] = bo[q][hh] * zf[q];
            }
            nbar_arrive(1, 512);             // bias(t) ready
        }
        nbar_sync(2, 512);                   // drain C's final arrive
    } else {
        // ================= C group: QK / softmax / AV =================
        const int h  = tid >> 5;             // warp = head
        const int g  = lane >> 2;
        const int t4 = lane & 3;
        const float QSC = 0.125f * LOG2E;

        float oacc[2][8][4];
#pragma unroll
        for (int mf = 0; mf < 2; mf++)
#pragma unroll
            for (int nf = 0; nf < 8; nf++)
#pragma unroll
                for (int r = 0; r < 4; r++) oacc[mf][nf][r] = 0.f;
        float mrun[2] = {-INFINITY, -INFINITY};
        float lrun[2] = {0.f, 0.f};

        for (int t = 0; t < 32; t++) {
            const int j0 = t * 32;

            // ---- stage K/V tile (256 C threads) ----
#pragma unroll
            for (int tt = tid; tt < 4096; tt += 256) {
                int jj = tt >> 7, c4 = (tt & 127) * 4;
                const float* src = qkv + ((size_t)(b * NN + j0 + jj)) * 1536;
                *(float4*)(k_s + jj * 524 + c4) =
                    *(const float4*)(src + 512 + c4);
                *(float4*)(v_s + jj * 524 + c4) =
                    *(const float4*)(src + 1024 + c4);
            }
            if (tid < 32)
                mask_s[tid] = kpm[(size_t)b * NN + j0 + tid] ? 1.f : 0.f;
            nbar_sync(3, 256);

            // ---- QK^T (per mf to bound registers) ----
#pragma unroll
            for (int mf = 0; mf < 2; mf++) {
                const float* q0 = qkv
                    + ((size_t)(b * NN + i0 + mf * 16 + g)) * 1536 + h * 64;
                const float* q8 = q0 + 8 * 1536;
                float c[4][4];
#pragma unroll
                for (int nf = 0; nf < 4; nf++)
#pragma unroll
                    for (int r = 0; r < 4; r++) c[nf][r] = 0.f;
#pragma unroll
                for (int ks = 0; ks < 8; ks++) {
                    uint ah[4], al[4];
                    split_tf32(q0[ks * 8 + t4]     * QSC, ah[0], al[0]);
                    split_tf32(q8[ks * 8 + t4]     * QSC, ah[1], al[1]);
                    split_tf32(q0[ks * 8 + t4 + 4] * QSC, ah[2], al[2]);
                    split_tf32(q8[ks * 8 + t4 + 4] * QSC, ah[3], al[3]);
#pragma unroll
                    for (int nf = 0; nf < 4; nf++) {
                        const float* kr =
                            k_s + (nf * 8 + g) * 524 + h * 64 + ks * 8;
                        uint bh0, bl0, bh1, bl1;
                        split_tf32(kr[t4],     bh0, bl0);
                        split_tf32(kr[t4 + 4], bh1, bl1);
                        mma_tf32(c[nf][0], c[nf][1], c[nf][2], c[nf][3],
                                 ah[0], ah[1], ah[2], ah[3], bh0, bh1);
                        mma_tf32(c[nf][0], c[nf][1], c[nf][2], c[nf][3],
                                 ah[0], ah[1], ah[2], ah[3], bl0, bl1);
                        mma_tf32(c[nf][0], c[nf][1], c[nf][2], c[nf][3],
                                 al[0], al[1], al[2], al[3], bh0, bh1);
                    }
                }
                const int rowL = (h * 32 + mf * 16 + g) * 36;
#pragma unroll
                for (int nf = 0; nf < 4; nf++) {
                    *(float2*)(lg_s + rowL + nf * 8 + 2 * t4) =
                        make_float2(c[nf][0], c[nf][1]);
                    *(float2*)(lg_s + rowL + 8 * 36 + nf * 8 + 2 * t4) =
                        make_float2(c[nf][2], c[nf][3]);
                }
            }
            __syncwarp();

            nbar_sync(1, 512);               // wait: bias(t) ready

            // ---- softmax (2 passes of 16 rows; 2 lanes per row) ----
#pragma unroll
            for (int p = 0; p < 2; p++) {
                const int row = p * 16 + (lane >> 1);
                const int sr  = h * 32 + row;
                const int co  = (lane & 1) * 16;
                const int bL  = sr * 36 + co;
                const int bBo = sr * 37 + co;
                float lg[16];
#pragma unroll
                for (int q = 0; q < 4; q++) {
                    float4 L = *(const float4*)(lg_s + bL + 4 * q);
                    lg[4*q+0] = L.x; lg[4*q+1] = L.y;
                    lg[4*q+2] = L.z; lg[4*q+3] = L.w;
                }
                float tmax = -INFINITY;
#pragma unroll
                for (int cc2 = 0; cc2 < 16; cc2++) {
                    float x = lg[cc2] + bias_s[bBo + cc2];
                    if (mask_s[co + cc2] > 0.5f) x = -1e30f;
                    lg[cc2] = x;
                    tmax = fmaxf(tmax, x);
                }
                tmax = fmaxf(tmax, __shfl_xor_sync(0xffffffffu, tmax, 1));
                float mnew = fmaxf(mrun[p], tmax);
                float corr = ex2(mrun[p] - mnew);
                mrun[p] = mnew;
                lrun[p] *= corr;
                float ps = 0.f;
#pragma unroll
                for (int q = 0; q < 4; q++) {
                    float4 P;
                    P.x = ex2(lg[4*q+0] - mnew);
                    P.y = ex2(lg[4*q+1] - mnew);
                    P.z = ex2(lg[4*q+2] - mnew);
                    P.w = ex2(lg[4*q+3] - mnew);
                    ps += (P.x + P.y) + (P.z + P.w);
                    *(float4*)(lg_s + bL + 4 * q) = P;
                }
                ps += __shfl_xor_sync(0xffffffffu, ps, 1);
                lrun[p] += ps;
                corr_s[sr] = corr;
            }
            __syncwarp();

            nbar_arrive(2, 512);             // bias buffer free for P

            // ---- AV (per mf) ----
#pragma unroll
            for (int mf = 0; mf < 2; mf++) {
                float corr0 = corr_s[h * 32 + mf * 16 + g];
                float corr1 = corr_s[h * 32 + mf * 16 + g + 8];
#pragma unroll
                for (int nf = 0; nf < 8; nf++) {
                    oacc[mf][nf][0] *= corr0; oacc[mf][nf][1] *= corr0;
                    oacc[mf][nf][2] *= corr1; oacc[mf][nf][3] *= corr1;
                }
                const int prow = (h * 32 + mf * 16 + g) * 36;
#pragma unroll
                for (int ks = 0; ks < 4; ks++) {
                    uint pah[4], pal[4];
                    split_tf32(lg_s[prow + ks * 8 + t4],          pah[0], pal[0]);
                    split_tf32(lg_s[prow + 288 + ks * 8 + t4],    pah[1], pal[1]);
                    split_tf32(lg_s[prow + ks * 8 + t4 + 4],      pah[2], pal[2]);
                    split_tf32(lg_s[prow + 288 + ks * 8 + t4 + 4],pah[3], pal[3]);
                    const float* vb0 = v_s + (ks * 8 + t4) * 524 + h * 64;
                    const float* vb1 = v_s + (ks * 8 + t4 + 4) * 524 + h * 64;
#pragma unroll
                    for (int nf = 0; nf < 8; nf++) {
                        uint bh0, bl0, bh1, bl1;
                        split_tf32(vb0[nf * 8 + g], bh0, bl0);
                        split_tf32(vb1[nf * 8 + g], bh1, bl1);
                        float* cc = oacc[mf][nf];
                        mma_tf32(cc[0], cc[1], cc[2], cc[3],
                                 pah[0], pah[1], pah[2], pah[3], bh0, bh1);
                        mma_tf32(cc[0], cc[1], cc[2], cc[3],
                                 pah[0], pah[1], pah[2], pah[3], bl0, bl1);
                        mma_tf32(cc[0], cc[1], cc[2], cc[3],
                                 pal[0], pal[1], pal[2], pal[3], bh0, bh1);
                    }
                }
            }
            nbar_sync(3, 256);               // k_s/v_s reusable
        }

        // ---- epilogue ----
        if ((lane & 1) == 0) {
            l_s[h * 32 + (lane >> 1)]      = lrun[0];
            l_s[h * 32 + 16 + (lane >> 1)] = lrun[1];
        }
        __syncwarp();
#pragma unroll
        for (int mf = 0; mf < 2; mf++) {
            float inv0 = 1.f / l_s[h * 32 + mf * 16 + g];
            float inv1 = 1.f / l_s[h * 32 + mf * 16 + g + 8];
            float* o0 = outp
                + ((size_t)(b * NN + i0 + mf * 16 + g)) * 512 + h * 64;
            float* o1 = o0 + 8 * 512;
#pragma unroll
            for (int nf = 0; nf < 8; nf++) {
                *(float2*)(o0 + nf * 8 + 2 * t4) =
                    make_float2(oacc[mf][nf][0] * inv0,
                                oacc[mf][nf][1] * inv0);
                *(float2*)(o1 + nf * 8 + 2 * t4) =
                    make_float2(oacc[mf][nf][2] * inv1,
                                oacc[mf][nf][3] * inv1);
            }
        }
    }
}

// ---------------------------------------------------------------------------
extern "C" void kernel_launch(void* const* d_in, const int* in_sizes, int n_in,
                              void* d_out, int out_size)
{
    const float* x      = (const float*)d_in[0];
    const float* coords = (const float*)d_in[1];
    const unsigned char* kpm = (const unsigned char*)d_in[2];
    const float* qkv_w  = (const float*)d_in[3];
    const float* out_w  = (const float*)d_in[4];
    const float* out_b  = (const float*)d_in[5];
    const float* alpha  = (const float*)d_in[6];
    const float* w1     = (const float*)d_in[7];
    const float* b1     = (const float*)d_in[8];
    const float* w2     = (const float*)d_in[9];
    const float* b2     = (const float*)d_in[10];
    const float* cs     = (const float*)d_in[11];
    float* out = (float*)d_out;

    float* qkvp = nullptr;
    float* attnp = nullptr;
    cudaGetSymbolAddress((void**)&qkvp, g_qkv);
    cudaGetSymbolAddress((void**)&attnp, g_attn);

    const int GSMEM = 2 * 10240 * 4;   // 81920 B (gemm)
    cudaFuncSetAttribute(gemm_tc,
                         cudaFuncAttributeMaxDynamicSharedMemorySize, GSMEM);
    const int SMEM = 53192 * 4;        // 212768 B (attention)
    cudaFuncSetAttribute(attn_bias_kernel,
                         cudaFuncAttributeMaxDynamicSharedMemorySize, SMEM);

    // 1) QKV projection: [8192,512] @ [512,1536]
    dim3 g1(1536 / 128, 8192 / 128);
    gemm_tc<<<g1, 256, GSMEM>>>(x, qkv_w, nullptr, qkvp, BB * NN, 3 * DM, DM);

    // 2) Fused bias + attention (warp-specialized producer/consumer)
    attn_bias_kernel<<<BB * (NN / 32), 512, SMEM>>>(
        qkvp, coords, kpm, w1, b1, w2, b2, cs, alpha, attnp);

    // 3) Output projection: [8192,512] @ [512,512] + bias
    dim3 g3(512 / 128, 8192 / 128);
    gemm_tc<<<g3, 256, GSMEM>>>(attnp, out_w, out_b, out, BB * NN, DM, DM);
}

// round 14
// speedup vs baseline: 1.6443x; 1.2316x over previous
#include <cuda_runtime.h>
#include <math.h>

#define BB 8
#define NN 1024
#define DM 512
#define NH 8
#define HD 64
#define NS_TOK 1

typedef unsigned int uint;

// Scratch (device globals: no allocations allowed in kernel_launch)
__device__ float g_qkv[(size_t)BB * NN * 3 * DM];   // [b][n][1536] : q|k|v
__device__ float g_attn[(size_t)BB * NN * DM];      // [b][n][512]

// ---------------------------------------------------------------------------
// tf32 split helpers (validated rounds 4-13)
// ---------------------------------------------------------------------------
__device__ __forceinline__ unsigned cvt_tf32(float x) {
    unsigned r;
    asm("cvt.rna.tf32.f32 %0, %1;" : "=r"(r) : "f"(x));
    return r;
}
__device__ __forceinline__ void split_tf32(float x, unsigned& hi, unsigned& lo) {
    hi = cvt_tf32(x);
    float rem = x - __uint_as_float(hi);
    lo = cvt_tf32(rem);
}
__device__ __forceinline__ void mma_tf32(
    float& c0, float& c1, float& c2, float& c3,
    unsigned a0, unsigned a1, unsigned a2, unsigned a3,
    unsigned b0, unsigned b1)
{
    asm("mma.sync.aligned.m16n8k8.row.col.f32.tf32.tf32.f32 "
        "{%0,%1,%2,%3}, {%4,%5,%6,%7}, {%8,%9}, {%0,%1,%2,%3};"
        : "+f"(c0), "+f"(c1), "+f"(c2), "+f"(c3)
        : "r"(a0), "r"(a1), "r"(a2), "r"(a3), "r"(b0), "r"(b1));
}

__device__ __forceinline__ float rcp_approx(float x) {
    float r;
    asm("rcp.approx.f32 %0, %1;" : "=f"(r) : "f"(x));
    return r;
}
__device__ __forceinline__ float ex2(float x) {
    float r;
    asm("ex2.approx.ftz.f32 %0, %1;" : "=f"(r) : "f"(x));
    return r;
}

// gelu with erf via Abramowitz-Stegun 7.1.28 (|err| <= 3e-7, 1 MUFU).
__device__ __forceinline__ float gelu_ns(float x) {
    float xs = x * 0.70710678118654752f;
    float ax = fabsf(xs);
    float t = 0.0000430638f;
    t = fmaf(t, ax, 0.0002765672f);
    t = fmaf(t, ax, 0.0001520143f);
    t = fmaf(t, ax, 0.0092705272f);
    t = fmaf(t, ax, 0.0422820123f);
    t = fmaf(t, ax, 0.0705230784f);
    t = fmaf(t, ax, 1.0f);
    float t2 = t * t;
    float t4 = t2 * t2;
    float t8 = t4 * t4;
    float t16 = t8 * t8;
    float er = 1.0f - rcp_approx(t16);
    er = copysignf(er, xs);
    return 0.5f * x * (1.0f + er);
}

// ---------------------------------------------------------------------------
// Tensor-core GEMM v3 (round-9, measured 250.9us). Unchanged.
// ---------------------------------------------------------------------------
#define RP 20   // u32 per smem row (16 data + 4 pad)

__global__ __launch_bounds__(256) void gemm_tc(
    const float* __restrict__ A, const float* __restrict__ W,
    const float* __restrict__ bias, float* __restrict__ C,
    int M, int Nc, int K)
{
    extern __shared__ uint gsm[];
    const int tid  = threadIdx.x;
    const int wid  = tid >> 5, lane = tid & 31;
    const int g    = lane >> 2, t4 = lane & 3;
    const int wm   = wid & 1,  wn  = wid >> 1;
    const int brow = blockIdx.y * 128, bcol = blockIdx.x * 128;
    const int m_base = wm * 64, n_base = wn * 32;
    const int m0 = tid >> 2, kq = (tid & 3) * 4;

    float c[4][4][4];
#pragma unroll
    for (int mf = 0; mf < 4; mf++)
#pragma unroll
        for (int nf = 0; nf < 4; nf++)
#pragma unroll
            for (int r = 0; r < 4; r++) c[mf][nf][r] = 0.f;

    float4 ra0, ra1, rw0, rw1;
    {
        ra0 = *(const float4*)(A + (size_t)(brow + m0) * K + kq);
        ra1 = *(const float4*)(A + (size_t)(brow + m0 + 64) * K + kq);
        rw0 = *(const float4*)(W + (size_t)(bcol + m0) * K + kq);
        rw1 = *(const float4*)(W + (size_t)(bcol + m0 + 64) * K + kq);
    }

    int buf = 0;
    for (int k0 = 0; k0 < K; k0 += 16) {
        uint* S = gsm + buf * 10240;
        {
            uint4 h, l;
            split_tf32(ra0.x, h.x, l.x); split_tf32(ra0.y, h.y, l.y);
            split_tf32(ra0.z, h.z, l.z); split_tf32(ra0.w, h.w, l.w);
            *(uint4*)&S[m0 * RP + kq] = h;
            *(uint4*)&S[2560 + m0 * RP + kq] = l;
            split_tf32(ra1.x, h.x, l.x); split_tf32(ra1.y, h.y, l.y);
            split_tf32(ra1.z, h.z, l.z); split_tf32(ra1.w, h.w, l.w);
            *(uint4*)&S[(m0 + 64) * RP + kq] = h;
            *(uint4*)&S[2560 + (m0 + 64) * RP + kq] = l;
            split_tf32(rw0.x, h.x, l.x); split_tf32(rw0.y, h.y, l.y);
            split_tf32(rw0.z, h.z, l.z); split_tf32(rw0.w, h.w, l.w);
            *(uint4*)&S[5120 + m0 * RP + kq] = h;
            *(uint4*)&S[7680 + m0 * RP + kq] = l;
            split_tf32(rw1.x, h.x, l.x); split_tf32(rw1.y, h.y, l.y);
            split_tf32(rw1.z, h.z, l.z); split_tf32(rw1.w, h.w, l.w);
            *(uint4*)&S[5120 + (m0 + 64) * RP + kq] = h;
            *(uint4*)&S[7680 + (m0 + 64) * RP + kq] = l;
        }
        __syncthreads();

        if (k0 + 16 < K) {
            int kn = k0 + 16 + kq;
            ra0 = *(const float4*)(A + (size_t)(brow + m0) * K + kn);
            ra1 = *(const float4*)(A + (size_t)(brow + m0 + 64) * K + kn);
            rw0 = *(const float4*)(W + (size_t)(bcol + m0) * K + kn);
            rw1 = *(const float4*)(W + (size_t)(bcol + m0 + 64) * K + kn);
        }

        const uint* Ah = S, *Al = S + 2560, *Wh = S + 5120, *Wl = S + 7680;
#pragma unroll
        for (int ks = 0; ks < 16; ks += 8) {
            unsigned ah[4][4], al[4][4];
#pragma unroll
            for (int mf = 0; mf < 4; mf++) {
                int r0 = (m_base + mf * 16 + g) * RP;
                int r1 = r0 + 8 * RP;
                ah[mf][0] = Ah[r0 + ks + t4];     al[mf][0] = Al[r0 + ks + t4];
                ah[mf][1] = Ah[r1 + ks + t4];     al[mf][1] = Al[r1 + ks + t4];
                ah[mf][2] = Ah[r0 + ks + t4 + 4]; al[mf][2] = Al[r0 + ks + t4 + 4];
                ah[mf][3] = Ah[r1 + ks + t4 + 4]; al[mf][3] = Al[r1 + ks + t4 + 4];
            }
            unsigned bh[4][2], bl[4][2];
#pragma unroll
            for (int nf = 0; nf < 4; nf++) {
                int rn = (n_base + nf * 8 + g) * RP;
                bh[nf][0] = Wh[rn + ks + t4];     bl[nf][0] = Wl[rn + ks + t4];
                bh[nf][1] = Wh[rn + ks + t4 + 4]; bl[nf][1] = Wl[rn + ks + t4 + 4];
            }
#pragma unroll
            for (int mf = 0; mf < 4; mf++)
#pragma unroll
                for (int nf = 0; nf < 4; nf++) {
                    float* cc = c[mf][nf];
                    mma_tf32(cc[0], cc[1], cc[2], cc[3],
                             ah[mf][0], ah[mf][1], ah[mf][2], ah[mf][3],
                             bh[nf][0], bh[nf][1]);
                    mma_tf32(cc[0], cc[1], cc[2], cc[3],
                             ah[mf][0], ah[mf][1], ah[mf][2], ah[mf][3],
                             bl[nf][0], bl[nf][1]);
                    mma_tf32(cc[0], cc[1], cc[2], cc[3],
                             al[mf][0], al[mf][1], al[mf][2], al[mf][3],
                             bh[nf][0], bh[nf][1]);
                }
        }
        buf ^= 1;
    }

#pragma unroll
    for (int mf = 0; mf < 4; mf++) {
        int row0 = brow + m_base + mf * 16 + g;
#pragma unroll
        for (int nf = 0; nf < 4; nf++) {
            int col = bcol + n_base + nf * 8 + 2 * t4;
            float b0 = 0.f, b1 = 0.f;
            if (bias) { b0 = bias[col]; b1 = bias[col + 1]; }
            float2 lo, hi;
            lo.x = c[mf][nf][0] + b0; lo.y = c[mf][nf][1] + b1;
            hi.x = c[mf][nf][2] + b0; hi.y = c[mf][nf][3] + b1;
            *(float2*)(C + (size_t)row0 * Nc + col) = lo;
            *(float2*)(C + (size_t)(row0 + 8) * Nc + col) = hi;
        }
    }
}

// ---------------------------------------------------------------------------
// Fused relative-position-bias attention (round-9 structure; AV uses a
// 2-term split: p_hi*v_hi + p_lo*v_hi. The dropped p*v_lo term is an
// incoherent 2^-12 rounding residual -> output rel err ~2.5e-4 (<< 1e-3).
// ---------------------------------------------------------------------------
#define LOG2E 1.4426950408889634f

__global__ __launch_bounds__(512, 1) void attn_bias_kernel(
    const float* __restrict__ qkv, const float* __restrict__ coords,
    const unsigned char* __restrict__ kpm,
    const float* __restrict__ w1, const float* __restrict__ b1,
    const float* __restrict__ w2, const float* __restrict__ b2,
    const float* __restrict__ cscales, const float* __restrict__ alphap,
    float* __restrict__ outp)
{
    extern __shared__ float sm[];
    float* k_s    = sm;            // [j][524]
    float* v_s    = sm + 16768;    // [j][524]
    float* bias_s = sm + 33536;    // [h][i][37]  (stride 37)
    float* lg_s   = sm + 43008;    // [h][i][36]
    float* corr_s = sm + 52224;    // 256
    float* l_s    = sm + 52480;    // 256
    float* ci_s   = sm + 52736;    // 32*4
    float* cj_s   = sm + 52864;    // 32*4
    float* w1_s   = sm + 52992;    // 128
    float* b1_s   = sm + 53120;    // 32
    float* w2t_s  = sm + 53152;    // [kk][8] alpha*log2e folded (256)
    float* b2_s   = sm + 53408;    // 8
    float* mask_s = sm + 53416;    // 32

    const int tid  = threadIdx.x;
    const int lane = tid & 31;
    const int wid  = tid >> 5;
    const int h    = wid >> 1;
    const int mh   = wid & 1;
    const int g    = lane >> 2;
    const int t4   = lane & 3;
    const int b    = blockIdx.x >> 5;
    const int i0   = (blockIdx.x & 31) * 32;
    const float alpha = alphap[0];

    const int sr     = tid >> 1;          // 0..255
    const int sjh    = (tid & 1) * 16;
    const int sbaseL = sr * 36;
    const int sbaseB = sr * 37;

    if (tid < 128) w1_s[tid] = w1[tid];
    if (tid < 32)  b1_s[tid] = b1[tid];
    if (tid < 256) w2t_s[tid] = alpha * LOG2E * w2[(tid & 7) * 32 + (tid >> 3)];
    if (tid < 8)   b2_s[tid] = alpha * LOG2E * b2[tid];
    if (tid < 32) {
        int ig = i0 + tid;
        ci_s[tid * 4 + 0] = coords[((size_t)b * NN + ig) * 3 + 0] / cscales[0];
        ci_s[tid * 4 + 1] = coords[((size_t)b * NN + ig) * 3 + 1] / cscales[1];
        ci_s[tid * 4 + 2] = coords[((size_t)b * NN + ig) * 3 + 2] / cscales[2];
        ci_s[tid * 4 + 3] = 0.f;
    }

    // Q elements feeding QK A-fragments (scale 1/8 * log2e folded)
    const float QSC = 0.125f * LOG2E;
    float qa[8][4];
    {
        const float* q0 = qkv + ((size_t)(b * NN + i0 + mh * 16 + g)) * 1536 + h * 64;
        const float* q8 = q0 + 8 * 1536;
#pragma unroll
        for (int ks = 0; ks < 8; ks++) {
            qa[ks][0] = q0[ks * 8 + t4]     * QSC;
            qa[ks][1] = q8[ks * 8 + t4]     * QSC;
            qa[ks][2] = q0[ks * 8 + t4 + 4] * QSC;
            qa[ks][3] = q8[ks * 8 + t4 + 4] * QSC;
        }
    }

    float oacc[8][4];
#pragma unroll
    for (int nf = 0; nf < 8; nf++)
#pragma unroll
        for (int r = 0; r < 4; r++) oacc[nf][r] = 0.f;
    float mrun = -INFINITY, lrun = 0.f;

    __syncthreads();

    for (int j0 = 0; j0 < NN; j0 += 32) {
        // ---- stage K/V tile (fp32) ----
#pragma unroll
        for (int t = tid; t < 4096; t += 512) {
            int jj = t >> 7, c4 = (t & 127) * 4;
            const float* src = qkv + ((size_t)(b * NN + j0 + jj)) * 1536;
            *(float4*)(k_s + jj * 524 + c4) = *(const float4*)(src + 512 + c4);
            *(float4*)(v_s + jj * 524 + c4) = *(const float4*)(src + 1024 + c4);
        }
        if (tid < 32) {
            int jg = j0 + tid;
            mask_s[tid] = kpm[(size_t)b * NN + jg] ? 1.f : 0.f;
            cj_s[tid * 4 + 0] = coords[((size_t)b * NN + jg) * 3 + 0] / cscales[0];
            cj_s[tid * 4 + 1] = coords[((size_t)b * NN + jg) * 3 + 1] / cscales[1];
            cj_s[tid * 4 + 2] = coords[((size_t)b * NN + jg) * 3 + 2] / cscales[2];
            cj_s[tid * 4 + 3] = 0.f;
        }
        __syncthreads();

        // ---- QK^T via tf32 split MMA (full 3-term: logits need it) ----
        {
            float c[4][4];
#pragma unroll
            for (int nf = 0; nf < 4; nf++)
#pragma unroll
                for (int r = 0; r < 4; r++) c[nf][r] = 0.f;
#pragma unroll
            for (int ks = 0; ks < 8; ks++) {
                uint ah[4], al[4];
                split_tf32(qa[ks][0], ah[0], al[0]);
                split_tf32(qa[ks][1], ah[1], al[1]);
                split_tf32(qa[ks][2], ah[2], al[2]);
                split_tf32(qa[ks][3], ah[3], al[3]);
#pragma unroll
                for (int nf = 0; nf < 4; nf++) {
                    const float* kr = k_s + (nf * 8 + g) * 524 + h * 64 + ks * 8;
                    uint bh0, bl0, bh1, bl1;
                    split_tf32(kr[t4],     bh0, bl0);
                    split_tf32(kr[t4 + 4], bh1, bl1);
                    mma_tf32(c[nf][0], c[nf][1], c[nf][2], c[nf][3],
                             ah[0], ah[1], ah[2], ah[3], bh0, bh1);
                    mma_tf32(c[nf][0], c[nf][1], c[nf][2], c[nf][3],
                             ah[0], ah[1], ah[2], ah[3], bl0, bl1);
                    mma_tf32(c[nf][0], c[nf][1], c[nf][2], c[nf][3],
                             al[0], al[1], al[2], al[3], bh0, bh1);
                }
            }
            const int rowL = h * 1152 + (mh * 16 + g) * 36;
#pragma unroll
            for (int nf = 0; nf < 4; nf++) {
                *(float2*)(lg_s + rowL + nf * 8 + 2 * t4) =
                    make_float2(c[nf][0], c[nf][1]);
                *(float2*)(lg_s + rowL + 8 * 36 + nf * 8 + 2 * t4) =
                    make_float2(c[nf][2], c[nf][3]);
            }
        }

        // ---- Phase A: bias MLP, both pairs fused (shared ii) ----
        {
            const int ii  = tid & 31;
            const int jj0 = tid >> 5;
            const int jj1 = jj0 + 16;
            const float cix = ci_s[ii * 4 + 0];
            const float ciy = ci_s[ii * 4 + 1];
            const float ciz = ci_s[ii * 4 + 2];
            const float dx0 = cix - cj_s[jj0 * 4 + 0];
            const float dy0 = ciy - cj_s[jj0 * 4 + 1];
            const float dz0 = ciz - cj_s[jj0 * 4 + 2];
            const float dx1 = cix - cj_s[jj1 * 4 + 0];
            const float dy1 = ciy - cj_s[jj1 * 4 + 1];
            const float dz1 = ciz - cj_s[jj1 * 4 + 2];
            const float di0 = sqrtf(fmaf(dx0, dx0, fmaf(dy0, dy0, dz0 * dz0)));
            const float di1 = sqrtf(fmaf(dx1, dx1, fmaf(dy1, dy1, dz1 * dz1)));

            float bo0[8], bo1[8];
#pragma unroll
            for (int hh = 0; hh < 8; hh++) { bo0[hh] = b2_s[hh]; bo1[hh] = b2_s[hh]; }

#pragma unroll 4
            for (int kk = 0; kk < 32; kk++) {
                float4 wv = *(const float4*)&w1_s[kk * 4];
                float bb  = b1_s[kk];
                float tA = bb, tB = bb;
                tA = fmaf(wv.x, dx0, tA); tA = fmaf(wv.y, dy0, tA);
                tA = fmaf(wv.z, dz0, tA); tA = fmaf(wv.w, di0, tA);
                tB = fmaf(wv.x, dx1, tB); tB = fmaf(wv.y, dy1, tB);
                tB = fmaf(wv.z, dz1, tB); tB = fmaf(wv.w, di1, tB);
                float g0 = gelu_ns(tA);
                float g1 = gelu_ns(tB);
                float4 wa = *(const float4*)&w2t_s[kk * 8];
                float4 wb = *(const float4*)&w2t_s[kk * 8 + 4];
                bo0[0] = fmaf(g0, wa.x, bo0[0]); bo1[0] = fmaf(g1, wa.x, bo1[0]);
                bo0[1] = fmaf(g0, wa.y, bo0[1]); bo1[1] = fmaf(g1, wa.y, bo1[1]);
                bo0[2] = fmaf(g0, wa.z, bo0[2]); bo1[2] = fmaf(g1, wa.z, bo1[2]);
                bo0[3] = fmaf(g0, wa.w, bo0[3]); bo1[3] = fmaf(g1, wa.w, bo1[3]);
                bo0[4] = fmaf(g0, wb.x, bo0[4]); bo1[4] = fmaf(g1, wb.x, bo1[4]);
                bo0[5] = fmaf(g0, wb.y, bo0[5]); bo1[5] = fmaf(g1, wb.y, bo1[5]);
                bo0[6] = fmaf(g0, wb.z, bo0[6]); bo1[6] = fmaf(g1, wb.z, bo1[6]);
                bo0[7] = fmaf(g0, wb.w, bo0[7]); bo1[7] = fmaf(g1, wb.w, bo1[7]);
            }

            const float zf0 =
                ((i0 + ii) >= NS_TOK && (j0 + jj0) >= NS_TOK) ? 1.f : 0.f;
            const float zf1 =
                ((i0 + ii) >= NS_TOK && (j0 + jj1) >= NS_TOK) ? 1.f : 0.f;
#pragma unroll
            for (int hh = 0; hh < 8; hh++) {
                bias_s[hh * 1184 + ii * 37 + jj0] = bo0[hh] * zf0;
                bias_s[hh * 1184 + ii * 37 + jj1] = bo1[hh] * zf1;
            }
        }
        __syncthreads();

        // ---- softmax (base-2): 2 threads per row; p in-place into lg_s ----
        {
            float lg[16];
            float4 L;
#pragma unroll
            for (int q = 0; q < 4; q++) {
                L = *(const float4*)(lg_s + sbaseL + sjh + 4 * q);
                lg[4*q+0] = L.x; lg[4*q+1] = L.y; lg[4*q+2] = L.z; lg[4*q+3] = L.w;
            }
            float tmax = -INFINITY;
#pragma unroll
            for (int c = 0; c < 16; c++) {
                float x = lg[c] + bias_s[sbaseB + sjh + c];
                if (mask_s[sjh + c] > 0.5f) x = -1e30f;
                lg[c] = x;
                tmax = fmaxf(tmax, x);
            }
            tmax = fmaxf(tmax, __shfl_xor_sync(0xffffffffu, tmax, 1));
            float mnew = fmaxf(mrun, tmax);
            float corr = ex2(mrun - mnew);
            mrun = mnew;
            lrun *= corr;
            float ps = 0.f;
#pragma unroll
            for (int q = 0; q < 4; q++) {
                float4 P;
                P.x = ex2(lg[4*q+0] - mrun);
                P.y = ex2(lg[4*q+1] - mrun);
                P.z = ex2(lg[4*q+2] - mrun);
                P.w = ex2(lg[4*q+3] - mrun);
                ps += (P.x + P.y) + (P.z + P.w);
                *(float4*)(lg_s + sbaseL + sjh + 4 * q) = P;
            }
            ps += __shfl_xor_sync(0xffffffffu, ps, 1);
            lrun += ps;
            corr_s[sr] = corr;
        }
        __syncthreads();

        // ---- AV via tf32 2-term split MMA (p_hi*v_hi + p_lo*v_hi) ----
        {
            float corr0 = corr_s[h * 32 + mh * 16 + g];
            float corr1 = corr_s[h * 32 + mh * 16 + g + 8];
#pragma unroll
            for (int nf = 0; nf < 8; nf++) {
                oacc[nf][0] *= corr0; oacc[nf][1] *= corr0;
                oacc[nf][2] *= corr1; oacc[nf][3] *= corr1;
            }
            const int prow = h * 1152 + (mh * 16 + g) * 36;
#pragma unroll
            for (int ks = 0; ks < 4; ks++) {
                uint pah[4], pal[4];
                split_tf32(lg_s[prow + ks * 8 + t4],              pah[0], pal[0]);
                split_tf32(lg_s[prow + 8 * 36 + ks * 8 + t4],     pah[1], pal[1]);
                split_tf32(lg_s[prow + ks * 8 + t4 + 4],          pah[2], pal[2]);
                split_tf32(lg_s[prow + 8 * 36 + ks * 8 + t4 + 4], pah[3], pal[3]);
                const float* vb0 = v_s + (ks * 8 + t4) * 524 + h * 64;
                const float* vb1 = v_s + (ks * 8 + t4 + 4) * 524 + h * 64;
#pragma unroll
                for (int nf = 0; nf < 8; nf++) {
                    uint bh0 = cvt_tf32(vb0[nf * 8 + g]);
                    uint bh1 = cvt_tf32(vb1[nf * 8 + g]);
                    mma_tf32(oacc[nf][0], oacc[nf][1], oacc[nf][2], oacc[nf][3],
                             pah[0], pah[1], pah[2], pah[3], bh0, bh1);
                    mma_tf32(oacc[nf][0], oacc[nf][1], oacc[nf][2], oacc[nf][3],
                             pal[0], pal[1], pal[2], pal[3], bh0, bh1);
                }
            }
        }
        __syncthreads();
    }

    if ((tid & 1) == 0) l_s[sr] = lrun;
    __syncthreads();

    {
        float inv0 = 1.f / l_s[h * 32 + mh * 16 + g];
        float inv1 = 1.f / l_s[h * 32 + mh * 16 + g + 8];
        float* o0 = outp + ((size_t)(b * NN + i0 + mh * 16 + g)) * 512 + h * 64;
        float* o1 = o0 + 8 * 512;
#pragma unroll
        for (int nf = 0; nf < 8; nf++) {
            *(float2*)(o0 + nf * 8 + 2 * t4) =
                make_float2(oacc[nf][0] * inv0, oacc[nf][1] * inv0);
            *(float2*)(o1 + nf * 8 + 2 * t4) =
                make_float2(oacc[nf][2] * inv1, oacc[nf][3] * inv1);
        }
    }
}

// ---------------------------------------------------------------------------
extern "C" void kernel_launch(void* const* d_in, const int* in_sizes, int n_in,
                              void* d_out, int out_size)
{
    const float* x      = (const float*)d_in[0];
    const float* coords = (const float*)d_in[1];
    const unsigned char* kpm = (const unsigned char*)d_in[2];
    const float* qkv_w  = (const float*)d_in[3];
    const float* out_w  = (const float*)d_in[4];
    const float* out_b  = (const float*)d_in[5];
    const float* alpha  = (const float*)d_in[6];
    const float* w1     = (const float*)d_in[7];
    const float* b1     = (const float*)d_in[8];
    const float* w2     = (const float*)d_in[9];
    const float* b2     = (const float*)d_in[10];
    const float* cs     = (const float*)d_in[11];
    float* out = (float*)d_out;

    float* qkvp = nullptr;
    float* attnp = nullptr;
    cudaGetSymbolAddress((void**)&qkvp, g_qkv);
    cudaGetSymbolAddress((void**)&attnp, g_attn);

    const int GSMEM = 2 * 10240 * 4;   // 81920 B (gemm)
    cudaFuncSetAttribute(gemm_tc,
                         cudaFuncAttributeMaxDynamicSharedMemorySize, GSMEM);
    const int SMEM = 53448 * 4;        // 213792 B (attention)
    cudaFuncSetAttribute(attn_bias_kernel,
                         cudaFuncAttributeMaxDynamicSharedMemorySize, SMEM);

    // 1) QKV projection: [8192,512] @ [512,1536]
    dim3 g1(1536 / 128, 8192 / 128);
    gemm_tc<<<g1, 256, GSMEM>>>(x, qkv_w, nullptr, qkvp, BB * NN, 3 * DM, DM);

    // 2) Fused bias + attention (round-9 + 2-term AV)
    attn_bias_kernel<<<BB * (NN / 32), 512, SMEM>>>(
        qkvp, coords, kpm, w1, b1, w2, b2, cs, alpha, attnp);

    // 3) Output projection: [8192,512] @ [512,512] + bias
    dim3 g3(512 / 128, 8192 / 128);
    gemm_tc<<<g3, 256, GSMEM>>>(attnp, out_w, out_b, out, BB * NN, DM, DM);
}

// round 15
// speedup vs baseline: 1.8526x; 1.1267x over previous
#include <cuda_runtime.h>
#include <math.h>

#define BB 8
#define NN 1024
#define DM 512
#define NH 8
#define HD 64
#define NS_TOK 1

typedef unsigned int uint;

// Scratch (device globals: no allocations allowed in kernel_launch)
__device__ float g_qkv[(size_t)BB * NN * 3 * DM];   // [b][n][1536] : q|k|v
__device__ float g_attn[(size_t)BB * NN * DM];      // [b][n][512]

// ---------------------------------------------------------------------------
// tf32 helpers (validated rounds 4-14)
// ---------------------------------------------------------------------------
__device__ __forceinline__ unsigned cvt_tf32(float x) {
    unsigned r;
    asm("cvt.rna.tf32.f32 %0, %1;" : "=r"(r) : "f"(x));
    return r;
}
__device__ __forceinline__ void split_tf32(float x, unsigned& hi, unsigned& lo) {
    hi = cvt_tf32(x);
    float rem = x - __uint_as_float(hi);
    lo = cvt_tf32(rem);
}
__device__ __forceinline__ void mma_tf32(
    float& c0, float& c1, float& c2, float& c3,
    unsigned a0, unsigned a1, unsigned a2, unsigned a3,
    unsigned b0, unsigned b1)
{
    asm("mma.sync.aligned.m16n8k8.row.col.f32.tf32.tf32.f32 "
        "{%0,%1,%2,%3}, {%4,%5,%6,%7}, {%8,%9}, {%0,%1,%2,%3};"
        : "+f"(c0), "+f"(c1), "+f"(c2), "+f"(c3)
        : "r"(a0), "r"(a1), "r"(a2), "r"(a3), "r"(b0), "r"(b1));
}

__device__ __forceinline__ float rcp_approx(float x) {
    float r;
    asm("rcp.approx.f32 %0, %1;" : "=f"(r) : "f"(x));
    return r;
}
__device__ __forceinline__ float ex2(float x) {
    float r;
    asm("ex2.approx.ftz.f32 %0, %1;" : "=f"(r) : "f"(x));
    return r;
}

// gelu with erf via Abramowitz-Stegun 7.1.28 (|err| <= 3e-7, 1 MUFU).
__device__ __forceinline__ float gelu_ns(float x) {
    float xs = x * 0.70710678118654752f;
    float ax = fabsf(xs);
    float t = 0.0000430638f;
    t = fmaf(t, ax, 0.0002765672f);
    t = fmaf(t, ax, 0.0001520143f);
    t = fmaf(t, ax, 0.0092705272f);
    t = fmaf(t, ax, 0.0422820123f);
    t = fmaf(t, ax, 0.0705230784f);
    t = fmaf(t, ax, 1.0f);
    float t2 = t * t;
    float t4 = t2 * t2;
    float t8 = t4 * t4;
    float t16 = t8 * t8;
    float er = 1.0f - rcp_approx(t16);
    er = copysignf(er, xs);
    return 0.5f * x * (1.0f + er);
}

// ---------------------------------------------------------------------------
// Tensor-core GEMM v5: 2-term split (A_hi*B_hi + A_hi*B_lo; A_lo dropped,
// ~2.8e-4 incoherent output contribution). A staged hi-only -> 3 arrays per
// buffer. 256 threads, double-buffered, one barrier per k-iter.
// Buffer layout (uints, stride 7680): Ah @0, Wh @2560, Wl @5120.
// ---------------------------------------------------------------------------
#define RP 20   // u32 per smem row (16 data + 4 pad)

__global__ __launch_bounds__(256) void gemm_tc(
    const float* __restrict__ A, const float* __restrict__ W,
    const float* __restrict__ bias, float* __restrict__ C,
    int M, int Nc, int K)
{
    extern __shared__ uint gsm[];
    const int tid  = threadIdx.x;
    const int wid  = tid >> 5, lane = tid & 31;
    const int g    = lane >> 2, t4 = lane & 3;
    const int wm   = wid & 1,  wn  = wid >> 1;
    const int brow = blockIdx.y * 128, bcol = blockIdx.x * 128;
    const int m_base = wm * 64, n_base = wn * 32;
    const int m0 = tid >> 2, kq = (tid & 3) * 4;

    float c[4][4][4];
#pragma unroll
    for (int mf = 0; mf < 4; mf++)
#pragma unroll
        for (int nf = 0; nf < 4; nf++)
#pragma unroll
            for (int r = 0; r < 4; r++) c[mf][nf][r] = 0.f;

    float4 ra0, ra1, rw0, rw1;
    {
        ra0 = *(const float4*)(A + (size_t)(brow + m0) * K + kq);
        ra1 = *(const float4*)(A + (size_t)(brow + m0 + 64) * K + kq);
        rw0 = *(const float4*)(W + (size_t)(bcol + m0) * K + kq);
        rw1 = *(const float4*)(W + (size_t)(bcol + m0 + 64) * K + kq);
    }

    int buf = 0;
    for (int k0 = 0; k0 < K; k0 += 16) {
        uint* S = gsm + buf * 7680;
        {
            uint4 h, l;
            // A: hi only
            h.x = cvt_tf32(ra0.x); h.y = cvt_tf32(ra0.y);
            h.z = cvt_tf32(ra0.z); h.w = cvt_tf32(ra0.w);
            *(uint4*)&S[m0 * RP + kq] = h;
            h.x = cvt_tf32(ra1.x); h.y = cvt_tf32(ra1.y);
            h.z = cvt_tf32(ra1.z); h.w = cvt_tf32(ra1.w);
            *(uint4*)&S[(m0 + 64) * RP + kq] = h;
            // W: hi + lo
            split_tf32(rw0.x, h.x, l.x); split_tf32(rw0.y, h.y, l.y);
            split_tf32(rw0.z, h.z, l.z); split_tf32(rw0.w, h.w, l.w);
            *(uint4*)&S[2560 + m0 * RP + kq] = h;
            *(uint4*)&S[5120 + m0 * RP + kq] = l;
            split_tf32(rw1.x, h.x, l.x); split_tf32(rw1.y, h.y, l.y);
            split_tf32(rw1.z, h.z, l.z); split_tf32(rw1.w, h.w, l.w);
            *(uint4*)&S[2560 + (m0 + 64) * RP + kq] = h;
            *(uint4*)&S[5120 + (m0 + 64) * RP + kq] = l;
        }
        __syncthreads();

        if (k0 + 16 < K) {
            int kn = k0 + 16 + kq;
            ra0 = *(const float4*)(A + (size_t)(brow + m0) * K + kn);
            ra1 = *(const float4*)(A + (size_t)(brow + m0 + 64) * K + kn);
            rw0 = *(const float4*)(W + (size_t)(bcol + m0) * K + kn);
            rw1 = *(const float4*)(W + (size_t)(bcol + m0 + 64) * K + kn);
        }

        const uint* Ah = S, *Wh = S + 2560, *Wl = S + 5120;
#pragma unroll
        for (int ks = 0; ks < 16; ks += 8) {
            unsigned ah[4][4];
#pragma unroll
            for (int mf = 0; mf < 4; mf++) {
                int r0 = (m_base + mf * 16 + g) * RP;
                int r1 = r0 + 8 * RP;
                ah[mf][0] = Ah[r0 + ks + t4];
                ah[mf][1] = Ah[r1 + ks + t4];
                ah[mf][2] = Ah[r0 + ks + t4 + 4];
                ah[mf][3] = Ah[r1 + ks + t4 + 4];
            }
            unsigned bh[4][2], bl[4][2];
#pragma unroll
            for (int nf = 0; nf < 4; nf++) {
                int rn = (n_base + nf * 8 + g) * RP;
                bh[nf][0] = Wh[rn + ks + t4];     bl[nf][0] = Wl[rn + ks + t4];
                bh[nf][1] = Wh[rn + ks + t4 + 4]; bl[nf][1] = Wl[rn + ks + t4 + 4];
            }
#pragma unroll
            for (int mf = 0; mf < 4; mf++)
#pragma unroll
                for (int nf = 0; nf < 4; nf++) {
                    float* cc = c[mf][nf];
                    mma_tf32(cc[0], cc[1], cc[2], cc[3],
                             ah[mf][0], ah[mf][1], ah[mf][2], ah[mf][3],
                             bh[nf][0], bh[nf][1]);
                    mma_tf32(cc[0], cc[1], cc[2], cc[3],
                             ah[mf][0], ah[mf][1], ah[mf][2], ah[mf][3],
                             bl[nf][0], bl[nf][1]);
                }
        }
        buf ^= 1;
    }

#pragma unroll
    for (int mf = 0; mf < 4; mf++) {
        int row0 = brow + m_base + mf * 16 + g;
#pragma unroll
        for (int nf = 0; nf < 4; nf++) {
            int col = bcol + n_base + nf * 8 + 2 * t4;
            float b0 = 0.f, b1 = 0.f;
            if (bias) { b0 = bias[col]; b1 = bias[col + 1]; }
            float2 lo, hi;
            lo.x = c[mf][nf][0] + b0; lo.y = c[mf][nf][1] + b1;
            hi.x = c[mf][nf][2] + b0; hi.y = c[mf][nf][3] + b1;
            *(float2*)(C + (size_t)row0 * Nc + col) = lo;
            *(float2*)(C + (size_t)(row0 + 8) * Nc + col) = hi;
        }
    }
}

// ---------------------------------------------------------------------------
// Fused relative-position-bias attention (round-14 structure; AV now
// SINGLE-term: p_hi * v_hi. QK keeps the full 3-term split (logit-sensitive).
// ---------------------------------------------------------------------------
#define LOG2E 1.4426950408889634f

__global__ __launch_bounds__(512, 1) void attn_bias_kernel(
    const float* __restrict__ qkv, const float* __restrict__ coords,
    const unsigned char* __restrict__ kpm,
    const float* __restrict__ w1, const float* __restrict__ b1,
    const float* __restrict__ w2, const float* __restrict__ b2,
    const float* __restrict__ cscales, const float* __restrict__ alphap,
    float* __restrict__ outp)
{
    extern __shared__ float sm[];
    float* k_s    = sm;            // [j][524]
    float* v_s    = sm + 16768;    // [j][524]
    float* bias_s = sm + 33536;    // [h][i][37]  (stride 37)
    float* lg_s   = sm + 43008;    // [h][i][36]
    float* corr_s = sm + 52224;    // 256
    float* l_s    = sm + 52480;    // 256
    float* ci_s   = sm + 52736;    // 32*4
    float* cj_s   = sm + 52864;    // 32*4
    float* w1_s   = sm + 52992;    // 128
    float* b1_s   = sm + 53120;    // 32
    float* w2t_s  = sm + 53152;    // [kk][8] alpha*log2e folded (256)
    float* b2_s   = sm + 53408;    // 8
    float* mask_s = sm + 53416;    // 32

    const int tid  = threadIdx.x;
    const int lane = tid & 31;
    const int wid  = tid >> 5;
    const int h    = wid >> 1;
    const int mh   = wid & 1;
    const int g    = lane >> 2;
    const int t4   = lane & 3;
    const int b    = blockIdx.x >> 5;
    const int i0   = (blockIdx.x & 31) * 32;
    const float alpha = alphap[0];

    const int sr     = tid >> 1;          // 0..255
    const int sjh    = (tid & 1) * 16;
    const int sbaseL = sr * 36;
    const int sbaseB = sr * 37;

    if (tid < 128) w1_s[tid] = w1[tid];
    if (tid < 32)  b1_s[tid] = b1[tid];
    if (tid < 256) w2t_s[tid] = alpha * LOG2E * w2[(tid & 7) * 32 + (tid >> 3)];
    if (tid < 8)   b2_s[tid] = alpha * LOG2E * b2[tid];
    if (tid < 32) {
        int ig = i0 + tid;
        ci_s[tid * 4 + 0] = coords[((size_t)b * NN + ig) * 3 + 0] / cscales[0];
        ci_s[tid * 4 + 1] = coords[((size_t)b * NN + ig) * 3 + 1] / cscales[1];
        ci_s[tid * 4 + 2] = coords[((size_t)b * NN + ig) * 3 + 2] / cscales[2];
        ci_s[tid * 4 + 3] = 0.f;
    }

    // Q elements feeding QK A-fragments (scale 1/8 * log2e folded)
    const float QSC = 0.125f * LOG2E;
    float qa[8][4];
    {
        const float* q0 = qkv + ((size_t)(b * NN + i0 + mh * 16 + g)) * 1536 + h * 64;
        const float* q8 = q0 + 8 * 1536;
#pragma unroll
        for (int ks = 0; ks < 8; ks++) {
            qa[ks][0] = q0[ks * 8 + t4]     * QSC;
            qa[ks][1] = q8[ks * 8 + t4]     * QSC;
            qa[ks][2] = q0[ks * 8 + t4 + 4] * QSC;
            qa[ks][3] = q8[ks * 8 + t4 + 4] * QSC;
        }
    }

    float oacc[8][4];
#pragma unroll
    for (int nf = 0; nf < 8; nf++)
#pragma unroll
        for (int r = 0; r < 4; r++) oacc[nf][r] = 0.f;
    float mrun = -INFINITY, lrun = 0.f;

    __syncthreads();

    for (int j0 = 0; j0 < NN; j0 += 32) {
        // ---- stage K/V tile (fp32) ----
#pragma unroll
        for (int t = tid; t < 4096; t += 512) {
            int jj = t >> 7, c4 = (t & 127) * 4;
            const float* src = qkv + ((size_t)(b * NN + j0 + jj)) * 1536;
            *(float4*)(k_s + jj * 524 + c4) = *(const float4*)(src + 512 + c4);
            *(float4*)(v_s + jj * 524 + c4) = *(const float4*)(src + 1024 + c4);
        }
        if (tid < 32) {
            int jg = j0 + tid;
            mask_s[tid] = kpm[(size_t)b * NN + jg] ? 1.f : 0.f;
            cj_s[tid * 4 + 0] = coords[((size_t)b * NN + jg) * 3 + 0] / cscales[0];
            cj_s[tid * 4 + 1] = coords[((size_t)b * NN + jg) * 3 + 1] / cscales[1];
            cj_s[tid * 4 + 2] = coords[((size_t)b * NN + jg) * 3 + 2] / cscales[2];
            cj_s[tid * 4 + 3] = 0.f;
        }
        __syncthreads();

        // ---- QK^T via tf32 split MMA (full 3-term: logits need it) ----
        {
            float c[4][4];
#pragma unroll
            for (int nf = 0; nf < 4; nf++)
#pragma unroll
                for (int r = 0; r < 4; r++) c[nf][r] = 0.f;
#pragma unroll
            for (int ks = 0; ks < 8; ks++) {
                uint ah[4], al[4];
                split_tf32(qa[ks][0], ah[0], al[0]);
                split_tf32(qa[ks][1], ah[1], al[1]);
                split_tf32(qa[ks][2], ah[2], al[2]);
                split_tf32(qa[ks][3], ah[3], al[3]);
#pragma unroll
                for (int nf = 0; nf < 4; nf++) {
                    const float* kr = k_s + (nf * 8 + g) * 524 + h * 64 + ks * 8;
                    uint bh0, bl0, bh1, bl1;
                    split_tf32(kr[t4],     bh0, bl0);
                    split_tf32(kr[t4 + 4], bh1, bl1);
                    mma_tf32(c[nf][0], c[nf][1], c[nf][2], c[nf][3],
                             ah[0], ah[1], ah[2], ah[3], bh0, bh1);
                    mma_tf32(c[nf][0], c[nf][1], c[nf][2], c[nf][3],
                             ah[0], ah[1], ah[2], ah[3], bl0, bl1);
                    mma_tf32(c[nf][0], c[nf][1], c[nf][2], c[nf][3],
                             al[0], al[1], al[2], al[3], bh0, bh1);
                }
            }
            const int rowL = h * 1152 + (mh * 16 + g) * 36;
#pragma unroll
            for (int nf = 0; nf < 4; nf++) {
                *(float2*)(lg_s + rowL + nf * 8 + 2 * t4) =
                    make_float2(c[nf][0], c[nf][1]);
                *(float2*)(lg_s + rowL + 8 * 36 + nf * 8 + 2 * t4) =
                    make_float2(c[nf][2], c[nf][3]);
            }
        }

        // ---- Phase A: bias MLP, both pairs fused (shared ii) ----
        {
            const int ii  = tid & 31;
            const int jj0 = tid >> 5;
            const int jj1 = jj0 + 16;
            const float cix = ci_s[ii * 4 + 0];
            const float ciy = ci_s[ii * 4 + 1];
            const float ciz = ci_s[ii * 4 + 2];
            const float dx0 = cix - cj_s[jj0 * 4 + 0];
            const float dy0 = ciy - cj_s[jj0 * 4 + 1];
            const float dz0 = ciz - cj_s[jj0 * 4 + 2];
            const float dx1 = cix - cj_s[jj1 * 4 + 0];
            const float dy1 = ciy - cj_s[jj1 * 4 + 1];
            const float dz1 = ciz - cj_s[jj1 * 4 + 2];
            const float di0 = sqrtf(fmaf(dx0, dx0, fmaf(dy0, dy0, dz0 * dz0)));
            const float di1 = sqrtf(fmaf(dx1, dx1, fmaf(dy1, dy1, dz1 * dz1)));

            float bo0[8], bo1[8];
#pragma unroll
            for (int hh = 0; hh < 8; hh++) { bo0[hh] = b2_s[hh]; bo1[hh] = b2_s[hh]; }

#pragma unroll 4
            for (int kk = 0; kk < 32; kk++) {
                float4 wv = *(const float4*)&w1_s[kk * 4];
                float bb  = b1_s[kk];
                float tA = bb, tB = bb;
                tA = fmaf(wv.x, dx0, tA); tA = fmaf(wv.y, dy0, tA);
                tA = fmaf(wv.z, dz0, tA); tA = fmaf(wv.w, di0, tA);
                tB = fmaf(wv.x, dx1, tB); tB = fmaf(wv.y, dy1, tB);
                tB = fmaf(wv.z, dz1, tB); tB = fmaf(wv.w, di1, tB);
                float g0 = gelu_ns(tA);
                float g1 = gelu_ns(tB);
                float4 wa = *(const float4*)&w2t_s[kk * 8];
                float4 wb = *(const float4*)&w2t_s[kk * 8 + 4];
                bo0[0] = fmaf(g0, wa.x, bo0[0]); bo1[0] = fmaf(g1, wa.x, bo1[0]);
                bo0[1] = fmaf(g0, wa.y, bo0[1]); bo1[1] = fmaf(g1, wa.y, bo1[1]);
                bo0[2] = fmaf(g0, wa.z, bo0[2]); bo1[2] = fmaf(g1, wa.z, bo1[2]);
                bo0[3] = fmaf(g0, wa.w, bo0[3]); bo1[3] = fmaf(g1, wa.w, bo1[3]);
                bo0[4] = fmaf(g0, wb.x, bo0[4]); bo1[4] = fmaf(g1, wb.x, bo1[4]);
                bo0[5] = fmaf(g0, wb.y, bo0[5]); bo1[5] = fmaf(g1, wb.y, bo1[5]);
                bo0[6] = fmaf(g0, wb.z, bo0[6]); bo1[6] = fmaf(g1, wb.z, bo1[6]);
                bo0[7] = fmaf(g0, wb.w, bo0[7]); bo1[7] = fmaf(g1, wb.w, bo1[7]);
            }

            const float zf0 =
                ((i0 + ii) >= NS_TOK && (j0 + jj0) >= NS_TOK) ? 1.f : 0.f;
            const float zf1 =
                ((i0 + ii) >= NS_TOK && (j0 + jj1) >= NS_TOK) ? 1.f : 0.f;
#pragma unroll
            for (int hh = 0; hh < 8; hh++) {
                bias_s[hh * 1184 + ii * 37 + jj0] = bo0[hh] * zf0;
                bias_s[hh * 1184 + ii * 37 + jj1] = bo1[hh] * zf1;
            }
        }
        __syncthreads();

        // ---- softmax (base-2): 2 threads per row; p in-place into lg_s ----
        {
            float lg[16];
            float4 L;
#pragma unroll
            for (int q = 0; q < 4; q++) {
                L = *(const float4*)(lg_s + sbaseL + sjh + 4 * q);
                lg[4*q+0] = L.x; lg[4*q+1] = L.y; lg[4*q+2] = L.z; lg[4*q+3] = L.w;
            }
            float tmax = -INFINITY;
#pragma unroll
            for (int c = 0; c < 16; c++) {
                float x = lg[c] + bias_s[sbaseB + sjh + c];
                if (mask_s[sjh + c] > 0.5f) x = -1e30f;
                lg[c] = x;
                tmax = fmaxf(tmax, x);
            }
            tmax = fmaxf(tmax, __shfl_xor_sync(0xffffffffu, tmax, 1));
            float mnew = fmaxf(mrun, tmax);
            float corr = ex2(mrun - mnew);
            mrun = mnew;
            lrun *= corr;
            float ps = 0.f;
#pragma unroll
            for (int q = 0; q < 4; q++) {
                float4 P;
                P.x = ex2(lg[4*q+0] - mrun);
                P.y = ex2(lg[4*q+1] - mrun);
                P.z = ex2(lg[4*q+2] - mrun);
                P.w = ex2(lg[4*q+3] - mrun);
                ps += (P.x + P.y) + (P.z + P.w);
                *(float4*)(lg_s + sbaseL + sjh + 4 * q) = P;
            }
            ps += __shfl_xor_sync(0xffffffffu, ps, 1);
            lrun += ps;
            corr_s[sr] = corr;
        }
        __syncthreads();

        // ---- AV via tf32 single-term MMA (p_hi * v_hi) ----
        {
            float corr0 = corr_s[h * 32 + mh * 16 + g];
            float corr1 = corr_s[h * 32 + mh * 16 + g + 8];
#pragma unroll
            for (int nf = 0; nf < 8; nf++) {
                oacc[nf][0] *= corr0; oacc[nf][1] *= corr0;
                oacc[nf][2] *= corr1; oacc[nf][3] *= corr1;
            }
            const int prow = h * 1152 + (mh * 16 + g) * 36;
#pragma unroll
            for (int ks = 0; ks < 4; ks++) {
                uint pah[4];
                pah[0] = cvt_tf32(lg_s[prow + ks * 8 + t4]);
                pah[1] = cvt_tf32(lg_s[prow + 8 * 36 + ks * 8 + t4]);
                pah[2] = cvt_tf32(lg_s[prow + ks * 8 + t4 + 4]);
                pah[3] = cvt_tf32(lg_s[prow + 8 * 36 + ks * 8 + t4 + 4]);
                const float* vb0 = v_s + (ks * 8 + t4) * 524 + h * 64;
                const float* vb1 = v_s + (ks * 8 + t4 + 4) * 524 + h * 64;
#pragma unroll
                for (int nf = 0; nf < 8; nf++) {
                    uint bh0 = cvt_tf32(vb0[nf * 8 + g]);
                    uint bh1 = cvt_tf32(vb1[nf * 8 + g]);
                    mma_tf32(oacc[nf][0], oacc[nf][1], oacc[nf][2], oacc[nf][3],
                             pah[0], pah[1], pah[2], pah[3], bh0, bh1);
                }
            }
        }
        __syncthreads();
    }

    if ((tid & 1) == 0) l_s[sr] = lrun;
    __syncthreads();

    {
        float inv0 = 1.f / l_s[h * 32 + mh * 16 + g];
        float inv1 = 1.f / l_s[h * 32 + mh * 16 + g + 8];
        float* o0 = outp + ((size_t)(b * NN + i0 + mh * 16 + g)) * 512 + h * 64;
        float* o1 = o0 + 8 * 512;
#pragma unroll
        for (int nf = 0; nf < 8; nf++) {
            *(float2*)(o0 + nf * 8 + 2 * t4) =
                make_float2(oacc[nf][0] * inv0, oacc[nf][1] * inv0);
            *(float2*)(o1 + nf * 8 + 2 * t4) =
                make_float2(oacc[nf][2] * inv1, oacc[nf][3] * inv1);
        }
    }
}

// ---------------------------------------------------------------------------
extern "C" void kernel_launch(void* const* d_in, const int* in_sizes, int n_in,
                              void* d_out, int out_size)
{
    const float* x      = (const float*)d_in[0];
    const float* coords = (const float*)d_in[1];
    const unsigned char* kpm = (const unsigned char*)d_in[2];
    const float* qkv_w  = (const float*)d_in[3];
    const float* out_w  = (const float*)d_in[4];
    const float* out_b  = (const float*)d_in[5];
    const float* alpha  = (const float*)d_in[6];
    const float* w1     = (const float*)d_in[7];
    const float* b1     = (const float*)d_in[8];
    const float* w2     = (const float*)d_in[9];
    const float* b2     = (const float*)d_in[10];
    const float* cs     = (const float*)d_in[11];
    float* out = (float*)d_out;

    float* qkvp = nullptr;
    float* attnp = nullptr;
    cudaGetSymbolAddress((void**)&qkvp, g_qkv);
    cudaGetSymbolAddress((void**)&attnp, g_attn);

    const int GSMEM = 2 * 7680 * 4;    // 61440 B (gemm, 2-term)
    cudaFuncSetAttribute(gemm_tc,
                         cudaFuncAttributeMaxDynamicSharedMemorySize, GSMEM);
    const int SMEM = 53448 * 4;        // 213792 B (attention)
    cudaFuncSetAttribute(attn_bias_kernel,
                         cudaFuncAttributeMaxDynamicSharedMemorySize, SMEM);

    // 1) QKV projection: [8192,512] @ [512,1536]  (2-term split)
    dim3 g1(1536 / 128, 8192 / 128);
    gemm_tc<<<g1, 256, GSMEM>>>(x, qkv_w, nullptr, qkvp, BB * NN, 3 * DM, DM);

    // 2) Fused bias + attention (1-term AV)
    attn_bias_kernel<<<BB * (NN / 32), 512, SMEM>>>(
        qkvp, coords, kpm, w1, b1, w2, b2, cs, alpha, attnp);

    // 3) Output projection: [8192,512] @ [512,512] + bias  (2-term split)
    dim3 g3(512 / 128, 8192 / 128);
    gemm_tc<<<g3, 256, GSMEM>>>(attnp, out_w, out_b, out, BB * NN, DM, DM);
}

// round 16
// speedup vs baseline: 2.0896x; 1.1279x over previous
#include <cuda_runtime.h>
#include <math.h>

#define BB 8
#define NN 1024
#define DM 512
#define NH 8
#define HD 64
#define NS_TOK 1

typedef unsigned int uint;

// Scratch (device globals: no allocations allowed in kernel_launch)
__device__ float g_qkv[(size_t)BB * NN * 3 * DM];   // [b][n][1536] : q|k|v
__device__ float g_attn[(size_t)BB * NN * DM];      // [b][n][512]

// ---------------------------------------------------------------------------
// tf32 helpers (validated rounds 4-15)
// ---------------------------------------------------------------------------
__device__ __forceinline__ unsigned cvt_tf32(float x) {
    unsigned r;
    asm("cvt.rna.tf32.f32 %0, %1;" : "=r"(r) : "f"(x));
    return r;
}
__device__ __forceinline__ void split_tf32(float x, unsigned& hi, unsigned& lo) {
    hi = cvt_tf32(x);
    float rem = x - __uint_as_float(hi);
    lo = cvt_tf32(rem);
}
__device__ __forceinline__ void mma_tf32(
    float& c0, float& c1, float& c2, float& c3,
    unsigned a0, unsigned a1, unsigned a2, unsigned a3,
    unsigned b0, unsigned b1)
{
    asm("mma.sync.aligned.m16n8k8.row.col.f32.tf32.tf32.f32 "
        "{%0,%1,%2,%3}, {%4,%5,%6,%7}, {%8,%9}, {%0,%1,%2,%3};"
        : "+f"(c0), "+f"(c1), "+f"(c2), "+f"(c3)
        : "r"(a0), "r"(a1), "r"(a2), "r"(a3), "r"(b0), "r"(b1));
}

__device__ __forceinline__ float rcp_approx(float x) {
    float r;
    asm("rcp.approx.f32 %0, %1;" : "=f"(r) : "f"(x));
    return r;
}
__device__ __forceinline__ float ex2(float x) {
    float r;
    asm("ex2.approx.ftz.f32 %0, %1;" : "=f"(r) : "f"(x));
    return r;
}

// gelu with erf via Abramowitz-Stegun 7.1.28 (|err| <= 3e-7, 1 MUFU).
__device__ __forceinline__ float gelu_ns(float x) {
    float xs = x * 0.70710678118654752f;
    float ax = fabsf(xs);
    float t = 0.0000430638f;
    t = fmaf(t, ax, 0.0002765672f);
    t = fmaf(t, ax, 0.0001520143f);
    t = fmaf(t, ax, 0.0092705272f);
    t = fmaf(t, ax, 0.0422820123f);
    t = fmaf(t, ax, 0.0705230784f);
    t = fmaf(t, ax, 1.0f);
    float t2 = t * t;
    float t4 = t2 * t2;
    float t8 = t4 * t4;
    float t16 = t8 * t8;
    float er = 1.0f - rcp_approx(t16);
    er = copysignf(er, xs);
    return 0.5f * x * (1.0f + er);
}

// ---------------------------------------------------------------------------
// Tensor-core GEMM v5 (round-15, measured 170us): 2-term split
// (A_hi*B_hi + A_hi*B_lo). Unchanged.
// ---------------------------------------------------------------------------
#define RP 20   // u32 per smem row (16 data + 4 pad)

__global__ __launch_bounds__(256) void gemm_tc(
    const float* __restrict__ A, const float* __restrict__ W,
    const float* __restrict__ bias, float* __restrict__ C,
    int M, int Nc, int K)
{
    extern __shared__ uint gsm[];
    const int tid  = threadIdx.x;
    const int wid  = tid >> 5, lane = tid & 31;
    const int g    = lane >> 2, t4 = lane & 3;
    const int wm   = wid & 1,  wn  = wid >> 1;
    const int brow = blockIdx.y * 128, bcol = blockIdx.x * 128;
    const int m_base = wm * 64, n_base = wn * 32;
    const int m0 = tid >> 2, kq = (tid & 3) * 4;

    float c[4][4][4];
#pragma unroll
    for (int mf = 0; mf < 4; mf++)
#pragma unroll
        for (int nf = 0; nf < 4; nf++)
#pragma unroll
            for (int r = 0; r < 4; r++) c[mf][nf][r] = 0.f;

    float4 ra0, ra1, rw0, rw1;
    {
        ra0 = *(const float4*)(A + (size_t)(brow + m0) * K + kq);
        ra1 = *(const float4*)(A + (size_t)(brow + m0 + 64) * K + kq);
        rw0 = *(const float4*)(W + (size_t)(bcol + m0) * K + kq);
        rw1 = *(const float4*)(W + (size_t)(bcol + m0 + 64) * K + kq);
    }

    int buf = 0;
    for (int k0 = 0; k0 < K; k0 += 16) {
        uint* S = gsm + buf * 7680;
        {
            uint4 h, l;
            h.x = cvt_tf32(ra0.x); h.y = cvt_tf32(ra0.y);
            h.z = cvt_tf32(ra0.z); h.w = cvt_tf32(ra0.w);
            *(uint4*)&S[m0 * RP + kq] = h;
            h.x = cvt_tf32(ra1.x); h.y = cvt_tf32(ra1.y);
            h.z = cvt_tf32(ra1.z); h.w = cvt_tf32(ra1.w);
            *(uint4*)&S[(m0 + 64) * RP + kq] = h;
            split_tf32(rw0.x, h.x, l.x); split_tf32(rw0.y, h.y, l.y);
            split_tf32(rw0.z, h.z, l.z); split_tf32(rw0.w, h.w, l.w);
            *(uint4*)&S[2560 + m0 * RP + kq] = h;
            *(uint4*)&S[5120 + m0 * RP + kq] = l;
            split_tf32(rw1.x, h.x, l.x); split_tf32(rw1.y, h.y, l.y);
            split_tf32(rw1.z, h.z, l.z); split_tf32(rw1.w, h.w, l.w);
            *(uint4*)&S[2560 + (m0 + 64) * RP + kq] = h;
            *(uint4*)&S[5120 + (m0 + 64) * RP + kq] = l;
        }
        __syncthreads();

        if (k0 + 16 < K) {
            int kn = k0 + 16 + kq;
            ra0 = *(const float4*)(A + (size_t)(brow + m0) * K + kn);
            ra1 = *(const float4*)(A + (size_t)(brow + m0 + 64) * K + kn);
            rw0 = *(const float4*)(W + (size_t)(bcol + m0) * K + kn);
            rw1 = *(const float4*)(W + (size_t)(bcol + m0 + 64) * K + kn);
        }

        const uint* Ah = S, *Wh = S + 2560, *Wl = S + 5120;
#pragma unroll
        for (int ks = 0; ks < 16; ks += 8) {
            unsigned ah[4][4];
#pragma unroll
            for (int mf = 0; mf < 4; mf++) {
                int r0 = (m_base + mf * 16 + g) * RP;
                int r1 = r0 + 8 * RP;
                ah[mf][0] = Ah[r0 + ks + t4];
                ah[mf][1] = Ah[r1 + ks + t4];
                ah[mf][2] = Ah[r0 + ks + t4 + 4];
                ah[mf][3] = Ah[r1 + ks + t4 + 4];
            }
            unsigned bh[4][2], bl[4][2];
#pragma unroll
            for (int nf = 0; nf < 4; nf++) {
                int rn = (n_base + nf * 8 + g) * RP;
                bh[nf][0] = Wh[rn + ks + t4];     bl[nf][0] = Wl[rn + ks + t4];
                bh[nf][1] = Wh[rn + ks + t4 + 4]; bl[nf][1] = Wl[rn + ks + t4 + 4];
            }
#pragma unroll
            for (int mf = 0; mf < 4; mf++)
#pragma unroll
                for (int nf = 0; nf < 4; nf++) {
                    float* cc = c[mf][nf];
                    mma_tf32(cc[0], cc[1], cc[2], cc[3],
                             ah[mf][0], ah[mf][1], ah[mf][2], ah[mf][3],
                             bh[nf][0], bh[nf][1]);
                    mma_tf32(cc[0], cc[1], cc[2], cc[3],
                             ah[mf][0], ah[mf][1], ah[mf][2], ah[mf][3],
                             bl[nf][0], bl[nf][1]);
                }
        }
        buf ^= 1;
    }

#pragma unroll
    for (int mf = 0; mf < 4; mf++) {
        int row0 = brow + m_base + mf * 16 + g;
#pragma unroll
        for (int nf = 0; nf < 4; nf++) {
            int col = bcol + n_base + nf * 8 + 2 * t4;
            float b0 = 0.f, b1 = 0.f;
            if (bias) { b0 = bias[col]; b1 = bias[col + 1]; }
            float2 lo, hi;
            lo.x = c[mf][nf][0] + b0; lo.y = c[mf][nf][1] + b1;
            hi.x = c[mf][nf][2] + b0; hi.y = c[mf][nf][3] + b1;
            *(float2*)(C + (size_t)row0 * Nc + col) = lo;
            *(float2*)(C + (size_t)(row0 + 8) * Nc + col) = hi;
        }
    }
}

// ---------------------------------------------------------------------------
// Fused relative-position-bias attention v13:
//  - QK^T: single-term tf32 MMA (q_hi * k_hi). K and V staged PRE-CONVERTED
//    to tf32 u32 in smem (cvt once at staging). Q converted once pre-loop.
//  - AV: single-term (p_hi * v_hi), v already tf32 in smem.
//  - Phase A / softmax identical to rounds 14/15.
// ---------------------------------------------------------------------------
#define LOG2E 1.4426950408889634f

__global__ __launch_bounds__(512, 1) void attn_bias_kernel(
    const float* __restrict__ qkv, const float* __restrict__ coords,
    const unsigned char* __restrict__ kpm,
    const float* __restrict__ w1, const float* __restrict__ b1,
    const float* __restrict__ w2, const float* __restrict__ b2,
    const float* __restrict__ cscales, const float* __restrict__ alphap,
    float* __restrict__ outp)
{
    extern __shared__ float sm[];
    uint*  k_u    = (uint*)sm;             // [j][524] tf32
    uint*  v_u    = (uint*)sm + 16768;     // [j][524] tf32
    float* bias_s = sm + 33536;    // [h][i][37]  (stride 37)
    float* lg_s   = sm + 43008;    // [h][i][36]
    float* corr_s = sm + 52224;    // 256
    float* l_s    = sm + 52480;    // 256
    float* ci_s   = sm + 52736;    // 32*4
    float* cj_s   = sm + 52864;    // 32*4
    float* w1_s   = sm + 52992;    // 128
    float* b1_s   = sm + 53120;    // 32
    float* w2t_s  = sm + 53152;    // [kk][8] alpha*log2e folded (256)
    float* b2_s   = sm + 53408;    // 8
    float* mask_s = sm + 53416;    // 32

    const int tid  = threadIdx.x;
    const int lane = tid & 31;
    const int wid  = tid >> 5;
    const int h    = wid >> 1;
    const int mh   = wid & 1;
    const int g    = lane >> 2;
    const int t4   = lane & 3;
    const int b    = blockIdx.x >> 5;
    const int i0   = (blockIdx.x & 31) * 32;
    const float alpha = alphap[0];

    const int sr     = tid >> 1;          // 0..255
    const int sjh    = (tid & 1) * 16;
    const int sbaseL = sr * 36;
    const int sbaseB = sr * 37;

    if (tid < 128) w1_s[tid] = w1[tid];
    if (tid < 32)  b1_s[tid] = b1[tid];
    if (tid < 256) w2t_s[tid] = alpha * LOG2E * w2[(tid & 7) * 32 + (tid >> 3)];
    if (tid < 8)   b2_s[tid] = alpha * LOG2E * b2[tid];
    if (tid < 32) {
        int ig = i0 + tid;
        ci_s[tid * 4 + 0] = coords[((size_t)b * NN + ig) * 3 + 0] / cscales[0];
        ci_s[tid * 4 + 1] = coords[((size_t)b * NN + ig) * 3 + 1] / cscales[1];
        ci_s[tid * 4 + 2] = coords[((size_t)b * NN + ig) * 3 + 2] / cscales[2];
        ci_s[tid * 4 + 3] = 0.f;
    }

    // Q fragments, tf32-converted ONCE (scale 1/8 * log2e folded)
    const float QSC = 0.125f * LOG2E;
    uint qh[8][4];
    {
        const float* q0 = qkv + ((size_t)(b * NN + i0 + mh * 16 + g)) * 1536 + h * 64;
        const float* q8 = q0 + 8 * 1536;
#pragma unroll
        for (int ks = 0; ks < 8; ks++) {
            qh[ks][0] = cvt_tf32(q0[ks * 8 + t4]     * QSC);
            qh[ks][1] = cvt_tf32(q8[ks * 8 + t4]     * QSC);
            qh[ks][2] = cvt_tf32(q0[ks * 8 + t4 + 4] * QSC);
            qh[ks][3] = cvt_tf32(q8[ks * 8 + t4 + 4] * QSC);
        }
    }

    float oacc[8][4];
#pragma unroll
    for (int nf = 0; nf < 8; nf++)
#pragma unroll
        for (int r = 0; r < 4; r++) oacc[nf][r] = 0.f;
    float mrun = -INFINITY, lrun = 0.f;

    __syncthreads();

    for (int j0 = 0; j0 < NN; j0 += 32) {
        // ---- stage K/V tile, pre-converted to tf32 ----
#pragma unroll
        for (int t = tid; t < 4096; t += 512) {
            int jj = t >> 7, c4 = (t & 127) * 4;
            const float* src = qkv + ((size_t)(b * NN + j0 + jj)) * 1536;
            float4 kf = *(const float4*)(src + 512 + c4);
            float4 vf = *(const float4*)(src + 1024 + c4);
            uint4 ku, vu;
            ku.x = cvt_tf32(kf.x); ku.y = cvt_tf32(kf.y);
            ku.z = cvt_tf32(kf.z); ku.w = cvt_tf32(kf.w);
            vu.x = cvt_tf32(vf.x); vu.y = cvt_tf32(vf.y);
            vu.z = cvt_tf32(vf.z); vu.w = cvt_tf32(vf.w);
            *(uint4*)(k_u + jj * 524 + c4) = ku;
            *(uint4*)(v_u + jj * 524 + c4) = vu;
        }
        if (tid < 32) {
            int jg = j0 + tid;
            mask_s[tid] = kpm[(size_t)b * NN + jg] ? 1.f : 0.f;
            cj_s[tid * 4 + 0] = coords[((size_t)b * NN + jg) * 3 + 0] / cscales[0];
            cj_s[tid * 4 + 1] = coords[((size_t)b * NN + jg) * 3 + 1] / cscales[1];
            cj_s[tid * 4 + 2] = coords[((size_t)b * NN + jg) * 3 + 2] / cscales[2];
            cj_s[tid * 4 + 3] = 0.f;
        }
        __syncthreads();

        // ---- QK^T via single-term tf32 MMA (32 MMAs, zero cvt in loop) ----
        {
            float c[4][4];
#pragma unroll
            for (int nf = 0; nf < 4; nf++)
#pragma unroll
                for (int r = 0; r < 4; r++) c[nf][r] = 0.f;
#pragma unroll
            for (int ks = 0; ks < 8; ks++) {
#pragma unroll
                for (int nf = 0; nf < 4; nf++) {
                    const uint* kr = k_u + (nf * 8 + g) * 524 + h * 64 + ks * 8;
                    mma_tf32(c[nf][0], c[nf][1], c[nf][2], c[nf][3],
                             qh[ks][0], qh[ks][1], qh[ks][2], qh[ks][3],
                             kr[t4], kr[t4 + 4]);
                }
            }
            const int rowL = h * 1152 + (mh * 16 + g) * 36;
#pragma unroll
            for (int nf = 0; nf < 4; nf++) {
                *(float2*)(lg_s + rowL + nf * 8 + 2 * t4) =
                    make_float2(c[nf][0], c[nf][1]);
                *(float2*)(lg_s + rowL + 8 * 36 + nf * 8 + 2 * t4) =
                    make_float2(c[nf][2], c[nf][3]);
            }
        }

        // ---- Phase A: bias MLP, both pairs fused (shared ii) ----
        {
            const int ii  = tid & 31;
            const int jj0 = tid >> 5;
            const int jj1 = jj0 + 16;
            const float cix = ci_s[ii * 4 + 0];
            const float ciy = ci_s[ii * 4 + 1];
            const float ciz = ci_s[ii * 4 + 2];
            const float dx0 = cix - cj_s[jj0 * 4 + 0];
            const float dy0 = ciy - cj_s[jj0 * 4 + 1];
            const float dz0 = ciz - cj_s[jj0 * 4 + 2];
            const float dx1 = cix - cj_s[jj1 * 4 + 0];
            const float dy1 = ciy - cj_s[jj1 * 4 + 1];
            const float dz1 = ciz - cj_s[jj1 * 4 + 2];
            const float di0 = sqrtf(fmaf(dx0, dx0, fmaf(dy0, dy0, dz0 * dz0)));
            const float di1 = sqrtf(fmaf(dx1, dx1, fmaf(dy1, dy1, dz1 * dz1)));

            float bo0[8], bo1[8];
#pragma unroll
            for (int hh = 0; hh < 8; hh++) { bo0[hh] = b2_s[hh]; bo1[hh] = b2_s[hh]; }

#pragma unroll 4
            for (int kk = 0; kk < 32; kk++) {
                float4 wv = *(const float4*)&w1_s[kk * 4];
                float bb  = b1_s[kk];
                float tA = bb, tB = bb;
                tA = fmaf(wv.x, dx0, tA); tA = fmaf(wv.y, dy0, tA);
                tA = fmaf(wv.z, dz0, tA); tA = fmaf(wv.w, di0, tA);
                tB = fmaf(wv.x, dx1, tB); tB = fmaf(wv.y, dy1, tB);
                tB = fmaf(wv.z, dz1, tB); tB = fmaf(wv.w, di1, tB);
                float g0 = gelu_ns(tA);
                float g1 = gelu_ns(tB);
                float4 wa = *(const float4*)&w2t_s[kk * 8];
                float4 wb = *(const float4*)&w2t_s[kk * 8 + 4];
                bo0[0] = fmaf(g0, wa.x, bo0[0]); bo1[0] = fmaf(g1, wa.x, bo1[0]);
                bo0[1] = fmaf(g0, wa.y, bo0[1]); bo1[1] = fmaf(g1, wa.y, bo1[1]);
                bo0[2] = fmaf(g0, wa.z, bo0[2]); bo1[2] = fmaf(g1, wa.z, bo1[2]);
                bo0[3] = fmaf(g0, wa.w, bo0[3]); bo1[3] = fmaf(g1, wa.w, bo1[3]);
                bo0[4] = fmaf(g0, wb.x, bo0[4]); bo1[4] = fmaf(g1, wb.x, bo1[4]);
                bo0[5] = fmaf(g0, wb.y, bo0[5]); bo1[5] = fmaf(g1, wb.y, bo1[5]);
                bo0[6] = fmaf(g0, wb.z, bo0[6]); bo1[6] = fmaf(g1, wb.z, bo1[6]);
                bo0[7] = fmaf(g0, wb.w, bo0[7]); bo1[7] = fmaf(g1, wb.w, bo1[7]);
            }

            const float zf0 =
                ((i0 + ii) >= NS_TOK && (j0 + jj0) >= NS_TOK) ? 1.f : 0.f;
            const float zf1 =
                ((i0 + ii) >= NS_TOK && (j0 + jj1) >= NS_TOK) ? 1.f : 0.f;
#pragma unroll
            for (int hh = 0; hh < 8; hh++) {
                bias_s[hh * 1184 + ii * 37 + jj0] = bo0[hh] * zf0;
                bias_s[hh * 1184 + ii * 37 + jj1] = bo1[hh] * zf1;
            }
        }
        __syncthreads();

        // ---- softmax (base-2): 2 threads per row; p in-place into lg_s ----
        {
            float lg[16];
            float4 L;
#pragma unroll
            for (int q = 0; q < 4; q++) {
                L = *(const float4*)(lg_s + sbaseL + sjh + 4 * q);
                lg[4*q+0] = L.x; lg[4*q+1] = L.y; lg[4*q+2] = L.z; lg[4*q+3] = L.w;
            }
            float tmax = -INFINITY;
#pragma unroll
            for (int c = 0; c < 16; c++) {
                float x = lg[c] + bias_s[sbaseB + sjh + c];
                if (mask_s[sjh + c] > 0.5f) x = -1e30f;
                lg[c] = x;
                tmax = fmaxf(tmax, x);
            }
            tmax = fmaxf(tmax, __shfl_xor_sync(0xffffffffu, tmax, 1));
            float mnew = fmaxf(mrun, tmax);
            float corr = ex2(mrun - mnew);
            mrun = mnew;
            lrun *= corr;
            float ps = 0.f;
#pragma unroll
            for (int q = 0; q < 4; q++) {
                float4 P;
                P.x = ex2(lg[4*q+0] - mrun);
                P.y = ex2(lg[4*q+1] - mrun);
                P.z = ex2(lg[4*q+2] - mrun);
                P.w = ex2(lg[4*q+3] - mrun);
                ps += (P.x + P.y) + (P.z + P.w);
                *(float4*)(lg_s + sbaseL + sjh + 4 * q) = P;
            }
            ps += __shfl_xor_sync(0xffffffffu, ps, 1);
            lrun += ps;
            corr_s[sr] = corr;
        }
        __syncthreads();

        // ---- AV via single-term tf32 MMA (p_hi * v_hi; v pre-cvt) ----
        {
            float corr0 = corr_s[h * 32 + mh * 16 + g];
            float corr1 = corr_s[h * 32 + mh * 16 + g + 8];
#pragma unroll
            for (int nf = 0; nf < 8; nf++) {
                oacc[nf][0] *= corr0; oacc[nf][1] *= corr0;
                oacc[nf][2] *= corr1; oacc[nf][3] *= corr1;
            }
            const int prow = h * 1152 + (mh * 16 + g) * 36;
#pragma unroll
            for (int ks = 0; ks < 4; ks++) {
                uint pah[4];
                pah[0] = cvt_tf32(lg_s[prow + ks * 8 + t4]);
                pah[1] = cvt_tf32(lg_s[prow + 8 * 36 + ks * 8 + t4]);
                pah[2] = cvt_tf32(lg_s[prow + ks * 8 + t4 + 4]);
                pah[3] = cvt_tf32(lg_s[prow + 8 * 36 + ks * 8 + t4 + 4]);
                const uint* vb0 = v_u + (ks * 8 + t4) * 524 + h * 64;
                const uint* vb1 = v_u + (ks * 8 + t4 + 4) * 524 + h * 64;
#pragma unroll
                for (int nf = 0; nf < 8; nf++) {
                    mma_tf32(oacc[nf][0], oacc[nf][1], oacc[nf][2], oacc[nf][3],
                             pah[0], pah[1], pah[2], pah[3],
                             vb0[nf * 8 + g], vb1[nf * 8 + g]);
                }
            }
        }
        __syncthreads();
    }

    if ((tid & 1) == 0) l_s[sr] = lrun;
    __syncthreads();

    {
        float inv0 = 1.f / l_s[h * 32 + mh * 16 + g];
        float inv1 = 1.f / l_s[h * 32 + mh * 16 + g + 8];
        float* o0 = outp + ((size_t)(b * NN + i0 + mh * 16 + g)) * 512 + h * 64;
        float* o1 = o0 + 8 * 512;
#pragma unroll
        for (int nf = 0; nf < 8; nf++) {
            *(float2*)(o0 + nf * 8 + 2 * t4) =
                make_float2(oacc[nf][0] * inv0, oacc[nf][1] * inv0);
            *(float2*)(o1 + nf * 8 + 2 * t4) =
                make_float2(oacc[nf][2] * inv1, oacc[nf][3] * inv1);
        }
    }
}

// ---------------------------------------------------------------------------
extern "C" void kernel_launch(void* const* d_in, const int* in_sizes, int n_in,
                              void* d_out, int out_size)
{
    const float* x      = (const float*)d_in[0];
    const float* coords = (const float*)d_in[1];
    const unsigned char* kpm = (const unsigned char*)d_in[2];
    const float* qkv_w  = (const float*)d_in[3];
    const float* out_w  = (const float*)d_in[4];
    const float* out_b  = (const float*)d_in[5];
    const float* alpha  = (const float*)d_in[6];
    const float* w1     = (const float*)d_in[7];
    const float* b1     = (const float*)d_in[8];
    const float* w2     = (const float*)d_in[9];
    const float* b2     = (const float*)d_in[10];
    const float* cs     = (const float*)d_in[11];
    float* out = (float*)d_out;

    float* qkvp = nullptr;
    float* attnp = nullptr;
    cudaGetSymbolAddress((void**)&qkvp, g_qkv);
    cudaGetSymbolAddress((void**)&attnp, g_attn);

    const int GSMEM = 2 * 7680 * 4;    // 61440 B (gemm, 2-term)
    cudaFuncSetAttribute(gemm_tc,
                         cudaFuncAttributeMaxDynamicSharedMemorySize, GSMEM);
    const int SMEM = 53448 * 4;        // 213792 B (attention)
    cudaFuncSetAttribute(attn_bias_kernel,
                         cudaFuncAttributeMaxDynamicSharedMemorySize, SMEM);

    // 1) QKV projection: [8192,512] @ [512,1536]  (2-term split)
    dim3 g1(1536 / 128, 8192 / 128);
    gemm_tc<<<g1, 256, GSMEM>>>(x, qkv_w, nullptr, qkvp, BB * NN, 3 * DM, DM);

    // 2) Fused bias + attention (1-term QK + 1-term AV, pre-cvt K/V)
    attn_bias_kernel<<<BB * (NN / 32), 512, SMEM>>>(
        qkvp, coords, kpm, w1, b1, w2, b2, cs, alpha, attnp);

    // 3) Output projection: [8192,512] @ [512,512] + bias  (2-term split)
    dim3 g3(512 / 128, 8192 / 128);
    gemm_tc<<<g3, 256, GSMEM>>>(attnp, out_w, out_b, out, BB * NN, DM, DM);
}